// round 5
// baseline (speedup 1.0000x reference)
#include <cuda_runtime.h>
#include <cuda_bf16.h>
#include <cstdint>

// ---------------- problem constants ----------------
static constexpr int BATCH    = 1024;
static constexpr int HIST     = 50;
static constexpr int N_ITEMS  = 100000;
static constexpr int IN_CH    = 64;

static constexpr int N_TILE   = 128;              // N per CTA
static constexpr int NPAD     = 100096;           // 782 * 128
static constexpr int N_CTAS   = NPAD / N_TILE;    // 782
static constexpr int M_TILE   = 128;
static constexpr int M_CHUNKS = BATCH / M_TILE;   // 8
static constexpr int SEGS     = 3;                // AhBh + AhBl + AlBh
static constexpr int KSEG     = 64;               // bf16 per seg (=128B row)
static constexpr int KROW     = SEGS * KSEG;      // 192 bf16 per logical row

static constexpr int SEG_B    = 128 * 128;        // bytes per seg tile (128 rows x 128B)
static constexpr int TILE_B   = SEGS * SEG_B;     // 49152
static constexpr int SMEM_A   = 0;
static constexpr int SMEM_B   = TILE_B;           // 49152
static constexpr int SMEM_TOTAL = 2 * TILE_B;     // 98304 -> 2 CTAs/SM

// scratch (device globals; allocation-free rule). g_B pad rows stay zero.
__device__ __align__(16) __nv_bfloat16 g_A[BATCH * KROW];
__device__ __align__(16) __nv_bfloat16 g_B[NPAD * KROW];

// ---------------- helpers ----------------
__device__ __forceinline__ uint32_t smem_u32(const void* p) {
    uint32_t a;
    asm("{ .reg .u64 t; cvta.to.shared.u64 t, %1; cvt.u32.u64 %0, t; }" : "=r"(a) : "l"(p));
    return a;
}
__device__ __forceinline__ void ldsm_x4(uint32_t addr, uint32_t& r0, uint32_t& r1,
                                        uint32_t& r2, uint32_t& r3) {
    asm volatile("ldmatrix.sync.aligned.m8n8.x4.shared.b16 {%0,%1,%2,%3}, [%4];"
                 : "=r"(r0), "=r"(r1), "=r"(r2), "=r"(r3) : "r"(addr));
}
__device__ __forceinline__ void mma16816(float* c, const uint32_t* a, uint32_t b0, uint32_t b1) {
    asm volatile(
        "mma.sync.aligned.m16n8k16.row.col.f32.bf16.bf16.f32 "
        "{%0,%1,%2,%3}, {%4,%5,%6,%7}, {%8,%9}, {%0,%1,%2,%3};"
        : "+f"(c[0]), "+f"(c[1]), "+f"(c[2]), "+f"(c[3])
        : "r"(a[0]), "r"(a[1]), "r"(a[2]), "r"(a[3]), "r"(b0), "r"(b1));
}

// ---------------- fused prep: init + split A + split B ----------------
__device__ __forceinline__ void split1(float x, __nv_bfloat16& h, __nv_bfloat16& l) {
    h = __float2bfloat16_rn(x);
    l = __float2bfloat16_rn(x - __bfloat162float(h));
}

static constexpr int PREP_B_WORK = NPAD * 16;     // 16 float4-quads per row
static constexpr int PREP_A_WORK = BATCH * 16;
static constexpr int PREP_TOTAL  = PREP_B_WORK + PREP_A_WORK;

__global__ void k_prep(const float* __restrict__ user_emb, const float* __restrict__ item_emb,
                       const int* __restrict__ uid, float* __restrict__ out) {
    int gid = blockIdx.x * blockDim.x + threadIdx.x;
    if (gid == 0) out[0] = 0.0f;
    if (gid < PREP_B_WORK) {
        int r = gid >> 4, q = gid & 15;
        if (r >= N_ITEMS) return;                   // pad rows stay zero
        float4 v = reinterpret_cast<const float4*>(item_emb)[(size_t)r * 16 + q];
        union { __nv_bfloat16 h[4]; uint2 u2; } H, L;
        split1(v.x, H.h[0], L.h[0]); split1(v.y, H.h[1], L.h[1]);
        split1(v.z, H.h[2], L.h[2]); split1(v.w, H.h[3], L.h[3]);
        __nv_bfloat16* row = g_B + (size_t)r * KROW + q * 4;
        *reinterpret_cast<uint2*>(row)       = H.u2;   // seg0: Bh
        *reinterpret_cast<uint2*>(row + 64)  = L.u2;   // seg1: Bl
        *reinterpret_cast<uint2*>(row + 128) = H.u2;   // seg2: Bh
    } else if (gid < PREP_TOTAL) {
        int t = gid - PREP_B_WORK;
        int b = t >> 4, q = t & 15;
        int u = uid[b];
        float4 v = reinterpret_cast<const float4*>(user_emb)[(size_t)u * 16 + q];
        union { __nv_bfloat16 h[4]; uint2 u2; } H, L;
        split1(v.x, H.h[0], L.h[0]); split1(v.y, H.h[1], L.h[1]);
        split1(v.z, H.h[2], L.h[2]); split1(v.w, H.h[3], L.h[3]);
        __nv_bfloat16* row = g_A + (size_t)b * KROW + q * 4;
        *reinterpret_cast<uint2*>(row)       = H.u2;   // seg0: Ah
        *reinterpret_cast<uint2*>(row + 64)  = H.u2;   // seg1: Ah
        *reinterpret_cast<uint2*>(row + 128) = L.u2;   // seg2: Al
    }
}

// ---------------- main GEMM + squares ----------------
// CTA: 256 thr = 8 warps, warp grid 2(M) x 4(N), warp tile 64x32. 2 CTAs/SM.
__global__ __launch_bounds__(256, 2) void k_gemm(float* __restrict__ out) {
    extern __shared__ char smem[];
    const uint32_t sb = smem_u32(smem);
    const uint32_t sA = sb + SMEM_A;
    const uint32_t sB = sb + SMEM_B;

    const int tid  = threadIdx.x, wid = tid >> 5, lane = tid & 31;
    const int wm   = wid & 1, wn = wid >> 1;
    const int n0   = blockIdx.x * N_TILE;
    const int la15 = lane & 15, half = lane >> 4;

    // --- load B tile [128 rows, 3 segs x 128B] with SW128 swizzle (persists) ---
    for (int i = tid; i < 128 * 24; i += 256) {
        int row = i / 24, r = i % 24, seg = r >> 3, c16 = r & 7;
        uint4 v = *reinterpret_cast<const uint4*>(
            g_B + (size_t)(n0 + row) * KROW + seg * KSEG + c16 * 8);
        *reinterpret_cast<uint4*>(smem + SMEM_B + seg * SEG_B +
                                  row * 128 + ((c16 * 16) ^ ((row & 7) * 16))) = v;
    }
    // --- load A tile for chunk 0 ---
    for (int i = tid; i < 128 * 24; i += 256) {
        int row = i / 24, r = i % 24, seg = r >> 3, c16 = r & 7;
        uint4 v = *reinterpret_cast<const uint4*>(
            g_A + (size_t)row * KROW + seg * KSEG + c16 * 8);
        *reinterpret_cast<uint4*>(smem + SMEM_A + seg * SEG_B +
                                  row * 128 + ((c16 * 16) ^ ((row & 7) * 16))) = v;
    }
    __syncthreads();

    float sq = 0.0f;

    for (int mc = 0; mc < M_CHUNKS; mc++) {
        const int m0 = mc * M_TILE;

        float acc[4][4][4];   // [mt][nt8][4]
        #pragma unroll
        for (int i = 0; i < 4; i++)
            #pragma unroll
            for (int j = 0; j < 4; j++)
                #pragma unroll
                for (int k = 0; k < 4; k++) acc[i][j][k] = 0.0f;

        #pragma unroll
        for (int seg = 0; seg < SEGS; seg++) {
            const uint32_t aSeg = sA + seg * SEG_B;
            const uint32_t bSeg = sB + seg * SEG_B;
            #pragma unroll
            for (int ks = 0; ks < 4; ks++) {        // 4 x k16 = K64 per seg
                const uint32_t koff = ks * 32 + half * 16;
                uint32_t a[4][4], b[2][4];
                #pragma unroll
                for (int mt = 0; mt < 4; mt++) {
                    int row = wm * 64 + mt * 16 + la15;
                    ldsm_x4(aSeg + row * 128 + (koff ^ ((row & 7) * 16)),
                            a[mt][0], a[mt][1], a[mt][2], a[mt][3]);
                }
                #pragma unroll
                for (int g = 0; g < 2; g++) {
                    int row = wn * 32 + g * 16 + la15;
                    ldsm_x4(bSeg + row * 128 + (koff ^ ((row & 7) * 16)),
                            b[g][0], b[g][1], b[g][2], b[g][3]);
                }
                #pragma unroll
                for (int mt = 0; mt < 4; mt++)
                    #pragma unroll
                    for (int g = 0; g < 2; g++) {
                        mma16816(acc[mt][2 * g],     a[mt], b[g][0], b[g][2]);
                        mma16816(acc[mt][2 * g + 1], a[mt], b[g][1], b[g][3]);
                    }
            }
        }
        __syncthreads();   // all warps done reading A tile

        // --- prefetch next A tile (overlaps with direct stores below) ---
        if (mc + 1 < M_CHUNKS) {
            const int m1 = (mc + 1) * M_TILE;
            for (int i = tid; i < 128 * 24; i += 256) {
                int row = i / 24, r = i % 24, seg = r >> 3, c16 = r & 7;
                uint4 v = *reinterpret_cast<const uint4*>(
                    g_A + (size_t)(m1 + row) * KROW + seg * KSEG + c16 * 8);
                *reinterpret_cast<uint4*>(smem + SMEM_A + seg * SEG_B +
                                          row * 128 + ((c16 * 16) ^ ((row & 7) * 16))) = v;
            }
        }

        // --- direct store epilogue (sector-efficient; out+1 is 4B-aligned) ---
        {
            const int r0    = m0 + wm * 64 + (lane >> 2);
            const int cbase = n0 + wn * 32 + 2 * (lane & 3);
            #pragma unroll
            for (int mt = 0; mt < 4; mt++) {
                float* rp = out + 1 + (size_t)(r0 + mt * 16) * N_ITEMS;
                #pragma unroll
                for (int nt = 0; nt < 4; nt++) {
                    const int c = cbase + nt * 8;
                    float v0 = acc[mt][nt][0], v1 = acc[mt][nt][1];
                    float v2 = acc[mt][nt][2], v3 = acc[mt][nt][3];
                    sq += v0 * v0 + v1 * v1 + v2 * v2 + v3 * v3;  // pad cols are exact 0
                    if (c < N_ITEMS) {
                        rp[c]     = v0;
                        rp[c + 1] = v1;
                        rp[c + (size_t)8 * N_ITEMS]     = v2;
                        rp[c + 1 + (size_t)8 * N_ITEMS] = v3;
                    }
                }
            }
        }
        __syncthreads();   // next A tile fully in smem
    }

    // reduce squares into loss
    #pragma unroll
    for (int o = 16; o > 0; o >>= 1) sq += __shfl_xor_sync(0xFFFFFFFFu, sq, o);
    if (lane == 0) atomicAdd(out, sq);
}

// ---------------- positives: + (1 - 2*s) per unique (row, item) ----------------
// 1 block per batch row, 4 warps; warp w handles j = w, w+4, ...
__global__ void k_pos(const float* __restrict__ user_emb, const float* __restrict__ item_emb,
                      const int* __restrict__ uid, const int* __restrict__ seq,
                      float* __restrict__ out) {
    const int b = blockIdx.x, tid = threadIdx.x;
    const int wid = tid >> 5, lane = tid & 31;
    __shared__ int   s_seq[HIST];
    __shared__ float s_u[IN_CH];
    __shared__ float s_part[4];
    if (tid < HIST)  s_seq[tid] = seq[b * HIST + tid];
    if (tid < IN_CH) s_u[tid]   = user_emb[(size_t)uid[b] * IN_CH + tid];
    if (tid < 4)     s_part[tid] = 0.0f;
    __syncthreads();

    const float u0 = s_u[2 * lane], u1 = s_u[2 * lane + 1];
    float acc = 0.0f;
    for (int j = wid; j < HIST; j += 4) {
        const int idx = s_seq[j];
        bool dup = false;
        for (int jj = 0; jj < j; jj++) dup |= (s_seq[jj] == idx);
        if (!dup) {
            float2 iv = reinterpret_cast<const float2*>(item_emb + (size_t)idx * IN_CH)[lane];
            float p = u0 * iv.x + u1 * iv.y;
            #pragma unroll
            for (int o = 16; o > 0; o >>= 1) p += __shfl_xor_sync(0xFFFFFFFFu, p, o);
            if (lane == 0) acc += 1.0f - 2.0f * p;
        }
    }
    if (lane == 0) s_part[wid] = acc;
    __syncthreads();
    if (tid == 0)
        atomicAdd(out, s_part[0] + s_part[1] + s_part[2] + s_part[3]);
}

// ---------------- launch ----------------
extern "C" void kernel_launch(void* const* d_in, const int* in_sizes, int n_in,
                              void* d_out, int out_size) {
    const float* user_emb = (const float*)d_in[0];
    const float* item_emb = (const float*)d_in[1];
    const int*   uid      = (const int*)d_in[2];
    const int*   seq      = (const int*)d_in[3];
    float*       out      = (float*)d_out;   // [0]=loss, [1..]=pref row-major

    cudaFuncSetAttribute(k_gemm, cudaFuncAttributeMaxDynamicSharedMemorySize, SMEM_TOTAL);

    k_prep<<<(PREP_TOTAL + 255) / 256, 256>>>(user_emb, item_emb, uid, out);
    k_gemm<<<N_CTAS, 256, SMEM_TOTAL>>>(out);
    k_pos<<<BATCH, 128>>>(user_emb, item_emb, uid, seq, out);
}

// round 6
// speedup vs baseline: 1.2721x; 1.2721x over previous
#include <cuda_runtime.h>
#include <cuda_bf16.h>
#include <cstdint>

// ---------------- problem constants ----------------
static constexpr int BATCH    = 1024;
static constexpr int HIST     = 50;
static constexpr int N_ITEMS  = 100000;
static constexpr int IN_CH    = 64;

static constexpr int N_TILE   = 128;              // N per CTA
static constexpr int NPAD     = 100096;           // 782 * 128
static constexpr int N_CTAS   = NPAD / N_TILE;    // 782
static constexpr int M_TILE   = 128;
static constexpr int M_CHUNKS = BATCH / M_TILE;   // 8
static constexpr int KSEG     = 64;               // bf16 per physical seg (=128B row)
static constexpr int KROW     = 2 * KSEG;         // 128 bf16 per row: [hi | lo]

static constexpr int SEG_B    = 128 * 128;        // bytes per seg tile (128 rows x 128B)
static constexpr int SMEM_A   = 0;                // Ah, Al           (32 KB)
static constexpr int SMEM_B   = 2 * SEG_B;        // Bh, Bl           (32 KB)
static constexpr int SMEM_STG = 4 * SEG_B;        // stage 128 x 65 f (33 KB)
static constexpr int STG_STRIDE = 65;
static constexpr int SMEM_TOTAL = SMEM_STG + 128 * STG_STRIDE * 4;   // 98816 -> 2 CTAs/SM

// scratch (device globals; allocation-free rule). g_B pad rows stay zero.
__device__ __align__(16) __nv_bfloat16 g_A[BATCH * KROW];
__device__ __align__(16) __nv_bfloat16 g_B[NPAD * KROW];

// ---------------- helpers ----------------
__device__ __forceinline__ uint32_t smem_u32(const void* p) {
    uint32_t a;
    asm("{ .reg .u64 t; cvta.to.shared.u64 t, %1; cvt.u32.u64 %0, t; }" : "=r"(a) : "l"(p));
    return a;
}
__device__ __forceinline__ void ldsm_x4(uint32_t addr, uint32_t& r0, uint32_t& r1,
                                        uint32_t& r2, uint32_t& r3) {
    asm volatile("ldmatrix.sync.aligned.m8n8.x4.shared.b16 {%0,%1,%2,%3}, [%4];"
                 : "=r"(r0), "=r"(r1), "=r"(r2), "=r"(r3) : "r"(addr));
}
__device__ __forceinline__ void mma16816(float* c, const uint32_t* a, uint32_t b0, uint32_t b1) {
    asm volatile(
        "mma.sync.aligned.m16n8k16.row.col.f32.bf16.bf16.f32 "
        "{%0,%1,%2,%3}, {%4,%5,%6,%7}, {%8,%9}, {%0,%1,%2,%3};"
        : "+f"(c[0]), "+f"(c[1]), "+f"(c[2]), "+f"(c[3])
        : "r"(a[0]), "r"(a[1]), "r"(a[2]), "r"(a[3]), "r"(b0), "r"(b1));
}
__device__ __forceinline__ void cp_async16(uint32_t saddr, const void* gptr) {
    asm volatile("cp.async.cg.shared.global [%0], [%1], 16;" :: "r"(saddr), "l"(gptr));
}
#define CP_COMMIT() asm volatile("cp.async.commit_group;" ::: "memory")
#define CP_WAIT0()  asm volatile("cp.async.wait_group 0;" ::: "memory")

// ---------------- fused prep: init + split A + split B ----------------
__device__ __forceinline__ void split1(float x, __nv_bfloat16& h, __nv_bfloat16& l) {
    h = __float2bfloat16_rn(x);
    l = __float2bfloat16_rn(x - __bfloat162float(h));
}

static constexpr int PREP_B_WORK = NPAD * 16;
static constexpr int PREP_A_WORK = BATCH * 16;
static constexpr int PREP_TOTAL  = PREP_B_WORK + PREP_A_WORK;

__global__ void k_prep(const float* __restrict__ user_emb, const float* __restrict__ item_emb,
                       const int* __restrict__ uid, float* __restrict__ out) {
    int gid = blockIdx.x * blockDim.x + threadIdx.x;
    if (gid == 0) out[0] = 0.0f;
    if (gid < PREP_B_WORK) {
        int r = gid >> 4, q = gid & 15;
        if (r >= N_ITEMS) return;                   // pad rows stay zero
        float4 v = reinterpret_cast<const float4*>(item_emb)[(size_t)r * 16 + q];
        union { __nv_bfloat16 h[4]; uint2 u2; } H, L;
        split1(v.x, H.h[0], L.h[0]); split1(v.y, H.h[1], L.h[1]);
        split1(v.z, H.h[2], L.h[2]); split1(v.w, H.h[3], L.h[3]);
        __nv_bfloat16* row = g_B + (size_t)r * KROW + q * 4;
        *reinterpret_cast<uint2*>(row)      = H.u2;   // Bh
        *reinterpret_cast<uint2*>(row + 64) = L.u2;   // Bl
    } else if (gid < PREP_TOTAL) {
        int t = gid - PREP_B_WORK;
        int b = t >> 4, q = t & 15;
        int u = uid[b];
        float4 v = reinterpret_cast<const float4*>(user_emb)[(size_t)u * 16 + q];
        union { __nv_bfloat16 h[4]; uint2 u2; } H, L;
        split1(v.x, H.h[0], L.h[0]); split1(v.y, H.h[1], L.h[1]);
        split1(v.z, H.h[2], L.h[2]); split1(v.w, H.h[3], L.h[3]);
        __nv_bfloat16* row = g_A + (size_t)b * KROW + q * 4;
        *reinterpret_cast<uint2*>(row)      = H.u2;   // Ah
        *reinterpret_cast<uint2*>(row + 64) = L.u2;   // Al
    }
}

// ---------------- main GEMM + squares ----------------
// CTA: 256 thr = 8 warps, warp grid 2(M) x 4(N), warp tile 64x32. 2 CTAs/SM.
__global__ __launch_bounds__(256, 2) void k_gemm(float* __restrict__ out) {
    extern __shared__ char smem[];
    const uint32_t sb = smem_u32(smem);
    const uint32_t sA = sb + SMEM_A;
    const uint32_t sB = sb + SMEM_B;
    float* stage = reinterpret_cast<float*>(smem + SMEM_STG);

    const int tid  = threadIdx.x, wid = tid >> 5, lane = tid & 31;
    const int wm   = wid & 1, wn = wid >> 1;
    const int n0   = blockIdx.x * N_TILE;
    const int la15 = lane & 15, half = lane >> 4;

    // --- load B tile [128 rows, 2 segs x 128B] with SW128 swizzle (persists) ---
    for (int i = tid; i < 128 * 16; i += 256) {
        int row = i >> 4, r = i & 15, seg = r >> 3, c16 = r & 7;
        uint4 v = *reinterpret_cast<const uint4*>(
            g_B + (size_t)(n0 + row) * KROW + seg * KSEG + c16 * 8);
        *reinterpret_cast<uint4*>(smem + SMEM_B + seg * SEG_B +
                                  row * 128 + ((c16 * 16) ^ ((row & 7) * 16))) = v;
    }
    // --- A chunk 0 via cp.async ---
    for (int i = tid; i < 128 * 16; i += 256) {
        int row = i >> 4, r = i & 15, seg = r >> 3, c16 = r & 7;
        cp_async16(sA + seg * SEG_B + row * 128 + ((c16 * 16) ^ ((row & 7) * 16)),
                   g_A + (size_t)row * KROW + seg * KSEG + c16 * 8);
    }
    CP_COMMIT();
    CP_WAIT0();
    __syncthreads();

    float sq = 0.0f;

    for (int mc = 0; mc < M_CHUNKS; mc++) {
        const int m0 = mc * M_TILE;

        float acc[4][4][4];   // [mt][nt8][4]
        #pragma unroll
        for (int i = 0; i < 4; i++)
            #pragma unroll
            for (int j = 0; j < 4; j++)
                #pragma unroll
                for (int k = 0; k < 4; k++) acc[i][j][k] = 0.0f;

        // segments: (Ah,Bh), (Ah,Bl), (Al,Bh)
        const uint32_t aOff[3] = {0, 0, SEG_B};
        const uint32_t bOff[3] = {0, SEG_B, 0};
        #pragma unroll
        for (int seg = 0; seg < 3; seg++) {
            const uint32_t aSeg = sA + aOff[seg];
            const uint32_t bSeg = sB + bOff[seg];
            #pragma unroll
            for (int ks = 0; ks < 4; ks++) {        // 4 x k16 = K64 per seg
                const uint32_t koff = ks * 32 + half * 16;
                uint32_t a[4][4], b[2][4];
                #pragma unroll
                for (int mt = 0; mt < 4; mt++) {
                    int row = wm * 64 + mt * 16 + la15;
                    ldsm_x4(aSeg + row * 128 + (koff ^ ((row & 7) * 16)),
                            a[mt][0], a[mt][1], a[mt][2], a[mt][3]);
                }
                #pragma unroll
                for (int g = 0; g < 2; g++) {
                    int row = wn * 32 + g * 16 + la15;
                    ldsm_x4(bSeg + row * 128 + (koff ^ ((row & 7) * 16)),
                            b[g][0], b[g][1], b[g][2], b[g][3]);
                }
                #pragma unroll
                for (int mt = 0; mt < 4; mt++)
                    #pragma unroll
                    for (int g = 0; g < 2; g++) {
                        mma16816(acc[mt][2 * g],     a[mt], b[g][0], b[g][2]);
                        mma16816(acc[mt][2 * g + 1], a[mt], b[g][1], b[g][3]);
                    }
            }
        }
        __syncthreads();   // all warps done reading A tile

        // --- prefetch next A tile via cp.async (overlaps whole epilogue) ---
        if (mc + 1 < M_CHUNKS) {
            const int m1 = (mc + 1) * M_TILE;
            for (int i = tid; i < 128 * 16; i += 256) {
                int row = i >> 4, r = i & 15, seg = r >> 3, c16 = r & 7;
                cp_async16(sA + seg * SEG_B + row * 128 + ((c16 * 16) ^ ((row & 7) * 16)),
                           g_A + (size_t)(m1 + row) * KROW + seg * KSEG + c16 * 8);
            }
            CP_COMMIT();
        }

        // --- staged epilogue: 2 pairs of 64 cols ---
        #pragma unroll
        for (int pair = 0; pair < 2; pair++) {
            if ((wn >> 1) == pair) {
                const int cbase = (wn & 1) * 32;
                #pragma unroll
                for (int mt = 0; mt < 4; mt++) {
                    int r0 = wm * 64 + mt * 16 + (lane >> 2);
                    #pragma unroll
                    for (int nt = 0; nt < 4; nt++) {
                        int c0 = cbase + nt * 8 + 2 * (lane & 3);
                        float v0 = acc[mt][nt][0], v1 = acc[mt][nt][1];
                        float v2 = acc[mt][nt][2], v3 = acc[mt][nt][3];
                        sq += v0 * v0 + v1 * v1 + v2 * v2 + v3 * v3;
                        stage[r0 * STG_STRIDE + c0]           = v0;
                        stage[r0 * STG_STRIDE + c0 + 1]       = v1;
                        stage[(r0 + 8) * STG_STRIDE + c0]     = v2;
                        stage[(r0 + 8) * STG_STRIDE + c0 + 1] = v3;
                    }
                }
            }
            __syncthreads();
            const int colg = n0 + pair * 64 + lane;
            float* op = out + 1 + (size_t)(m0 + wid * 16) * N_ITEMS;
            #pragma unroll
            for (int r = 0; r < 16; r++) {
                float* rp = op + (size_t)r * N_ITEMS;
                float s0 = stage[(wid * 16 + r) * STG_STRIDE + lane];
                float s1 = stage[(wid * 16 + r) * STG_STRIDE + lane + 32];
                if (colg < N_ITEMS)      rp[colg]      = s0;
                if (colg + 32 < N_ITEMS) rp[colg + 32] = s1;
            }
            if (pair == 0) __syncthreads();   // stores read stage before pair1 overwrites
        }

        CP_WAIT0();
        __syncthreads();   // next A tile fully in smem
    }

    // reduce squares into loss (pad cols contribute exactly 0)
    #pragma unroll
    for (int o = 16; o > 0; o >>= 1) sq += __shfl_xor_sync(0xFFFFFFFFu, sq, o);
    if (lane == 0) atomicAdd(out, sq);
}

// ---------------- positives: + (1 - 2*s) per unique (row, item) ----------------
__global__ void k_pos(const float* __restrict__ user_emb, const float* __restrict__ item_emb,
                      const int* __restrict__ uid, const int* __restrict__ seq,
                      float* __restrict__ out) {
    const int b = blockIdx.x, tid = threadIdx.x;
    const int wid = tid >> 5, lane = tid & 31;
    __shared__ int   s_seq[HIST];
    __shared__ float s_u[IN_CH];
    __shared__ float s_part[4];
    if (tid < HIST)  s_seq[tid] = seq[b * HIST + tid];
    if (tid < IN_CH) s_u[tid]   = user_emb[(size_t)uid[b] * IN_CH + tid];
    if (tid < 4)     s_part[tid] = 0.0f;
    __syncthreads();

    const float u0 = s_u[2 * lane], u1 = s_u[2 * lane + 1];
    float acc = 0.0f;
    for (int j = wid; j < HIST; j += 4) {
        const int idx = s_seq[j];
        bool dup = false;
        for (int jj = 0; jj < j; jj++) dup |= (s_seq[jj] == idx);
        if (!dup) {
            float2 iv = reinterpret_cast<const float2*>(item_emb + (size_t)idx * IN_CH)[lane];
            float p = u0 * iv.x + u1 * iv.y;
            #pragma unroll
            for (int o = 16; o > 0; o >>= 1) p += __shfl_xor_sync(0xFFFFFFFFu, p, o);
            if (lane == 0) acc += 1.0f - 2.0f * p;
        }
    }
    if (lane == 0) s_part[wid] = acc;
    __syncthreads();
    if (tid == 0)
        atomicAdd(out, s_part[0] + s_part[1] + s_part[2] + s_part[3]);
}

// ---------------- launch ----------------
extern "C" void kernel_launch(void* const* d_in, const int* in_sizes, int n_in,
                              void* d_out, int out_size) {
    const float* user_emb = (const float*)d_in[0];
    const float* item_emb = (const float*)d_in[1];
    const int*   uid      = (const int*)d_in[2];
    const int*   seq      = (const int*)d_in[3];
    float*       out      = (float*)d_out;   // [0]=loss, [1..]=pref row-major

    cudaFuncSetAttribute(k_gemm, cudaFuncAttributeMaxDynamicSharedMemorySize, SMEM_TOTAL);

    k_prep<<<(PREP_TOTAL + 255) / 256, 256>>>(user_emb, item_emb, uid, out);
    k_gemm<<<N_CTAS, 256, SMEM_TOTAL>>>(out);
    k_pos<<<BATCH, 128>>>(user_emb, item_emb, uid, seq, out);
}

// round 7
// speedup vs baseline: 1.4840x; 1.1666x over previous
#include <cuda_runtime.h>
#include <cuda_bf16.h>
#include <cstdint>

// ---------------- problem constants ----------------
static constexpr int BATCH    = 1024;
static constexpr int HIST     = 50;
static constexpr int N_ITEMS  = 100000;
static constexpr int IN_CH    = 64;

static constexpr int N_TILE   = 128;              // N per CTA
static constexpr int NPAD     = 100096;           // 782 * 128
static constexpr int N_CTAS   = NPAD / N_TILE;    // 782
static constexpr int M_TILE   = 128;
static constexpr int M_CHUNKS = BATCH / M_TILE;   // 8
static constexpr int KSEG     = 64;               // bf16 per physical seg (=128B row)
static constexpr int KROW     = 2 * KSEG;         // 128 bf16 per row: [hi | lo]

static constexpr int SEG_B    = 128 * 128;        // bytes per seg tile (128 rows x 128B)
static constexpr int SMEM_A   = 0;                // Ah, Al           (32 KB)
static constexpr int SMEM_B   = 2 * SEG_B;        // Bh, Bl           (32 KB)
static constexpr int SMEM_STG = 4 * SEG_B;        // stage 128 x 65 f (33 KB)
static constexpr int STG_STRIDE = 65;
static constexpr int SMEM_TOTAL = SMEM_STG + 128 * STG_STRIDE * 4;   // 98816 -> 2 CTAs/SM

// scratch (device globals; allocation-free rule). g_B pad rows stay zero.
__device__ __align__(16) __nv_bfloat16 g_A[BATCH * KROW];
__device__ __align__(16) __nv_bfloat16 g_B[NPAD * KROW];

// ---------------- helpers ----------------
__device__ __forceinline__ uint32_t smem_u32(const void* p) {
    uint32_t a;
    asm("{ .reg .u64 t; cvta.to.shared.u64 t, %1; cvt.u32.u64 %0, t; }" : "=r"(a) : "l"(p));
    return a;
}
__device__ __forceinline__ void ldsm_x4(uint32_t addr, uint32_t& r0, uint32_t& r1,
                                        uint32_t& r2, uint32_t& r3) {
    asm volatile("ldmatrix.sync.aligned.m8n8.x4.shared.b16 {%0,%1,%2,%3}, [%4];"
                 : "=r"(r0), "=r"(r1), "=r"(r2), "=r"(r3) : "r"(addr));
}
__device__ __forceinline__ void mma16816(float* c, const uint32_t* a, uint32_t b0, uint32_t b1) {
    asm volatile(
        "mma.sync.aligned.m16n8k16.row.col.f32.bf16.bf16.f32 "
        "{%0,%1,%2,%3}, {%4,%5,%6,%7}, {%8,%9}, {%0,%1,%2,%3};"
        : "+f"(c[0]), "+f"(c[1]), "+f"(c[2]), "+f"(c[3])
        : "r"(a[0]), "r"(a[1]), "r"(a[2]), "r"(a[3]), "r"(b0), "r"(b1));
}
__device__ __forceinline__ void cp_async16(uint32_t saddr, const void* gptr) {
    asm volatile("cp.async.cg.shared.global [%0], [%1], 16;" :: "r"(saddr), "l"(gptr));
}
#define CP_COMMIT() asm volatile("cp.async.commit_group;" ::: "memory")
#define CP_WAIT0()  asm volatile("cp.async.wait_group 0;" ::: "memory")

// ---------------- fused prep: init + split A + split B ----------------
__device__ __forceinline__ void split1(float x, __nv_bfloat16& h, __nv_bfloat16& l) {
    h = __float2bfloat16_rn(x);
    l = __float2bfloat16_rn(x - __bfloat162float(h));
}

static constexpr int PREP_B_WORK = NPAD * 16;
static constexpr int PREP_A_WORK = BATCH * 16;
static constexpr int PREP_TOTAL  = PREP_B_WORK + PREP_A_WORK;

__global__ void k_prep(const float* __restrict__ user_emb, const float* __restrict__ item_emb,
                       const int* __restrict__ uid, float* __restrict__ out) {
    int gid = blockIdx.x * blockDim.x + threadIdx.x;
    if (gid == 0) out[0] = 0.0f;
    if (gid < PREP_B_WORK) {
        int r = gid >> 4, q = gid & 15;
        if (r >= N_ITEMS) return;                   // pad rows stay zero
        float4 v = reinterpret_cast<const float4*>(item_emb)[(size_t)r * 16 + q];
        union { __nv_bfloat16 h[4]; uint2 u2; } H, L;
        split1(v.x, H.h[0], L.h[0]); split1(v.y, H.h[1], L.h[1]);
        split1(v.z, H.h[2], L.h[2]); split1(v.w, H.h[3], L.h[3]);
        __nv_bfloat16* row = g_B + (size_t)r * KROW + q * 4;
        *reinterpret_cast<uint2*>(row)      = H.u2;   // Bh
        *reinterpret_cast<uint2*>(row + 64) = L.u2;   // Bl
    } else if (gid < PREP_TOTAL) {
        int t = gid - PREP_B_WORK;
        int b = t >> 4, q = t & 15;
        int u = uid[b];
        float4 v = reinterpret_cast<const float4*>(user_emb)[(size_t)u * 16 + q];
        union { __nv_bfloat16 h[4]; uint2 u2; } H, L;
        split1(v.x, H.h[0], L.h[0]); split1(v.y, H.h[1], L.h[1]);
        split1(v.z, H.h[2], L.h[2]); split1(v.w, H.h[3], L.h[3]);
        __nv_bfloat16* row = g_A + (size_t)b * KROW + q * 4;
        *reinterpret_cast<uint2*>(row)      = H.u2;   // Ah
        *reinterpret_cast<uint2*>(row + 64) = L.u2;   // Al
    }
}

// ---------------- main GEMM + squares ----------------
// CTA: 256 thr = 8 warps, warp grid 2(M) x 4(N), warp tile 64x32. 2 CTAs/SM.
__global__ __launch_bounds__(256, 2) void k_gemm(float* __restrict__ out) {
    extern __shared__ char smem[];
    const uint32_t sb = smem_u32(smem);
    const uint32_t sA = sb + SMEM_A;
    const uint32_t sB = sb + SMEM_B;
    float* stage = reinterpret_cast<float*>(smem + SMEM_STG);

    const int tid  = threadIdx.x, wid = tid >> 5, lane = tid & 31;
    const int wm   = wid & 1, wn = wid >> 1;
    const int n0   = blockIdx.x * N_TILE;
    const int la15 = lane & 15, half = lane >> 4;

    // --- load B tile [128 rows, 2 segs x 128B] with SW128 swizzle (persists) ---
    for (int i = tid; i < 128 * 16; i += 256) {
        int row = i >> 4, r = i & 15, seg = r >> 3, c16 = r & 7;
        uint4 v = *reinterpret_cast<const uint4*>(
            g_B + (size_t)(n0 + row) * KROW + seg * KSEG + c16 * 8);
        *reinterpret_cast<uint4*>(smem + SMEM_B + seg * SEG_B +
                                  row * 128 + ((c16 * 16) ^ ((row & 7) * 16))) = v;
    }
    // --- A chunk 0 via cp.async ---
    for (int i = tid; i < 128 * 16; i += 256) {
        int row = i >> 4, r = i & 15, seg = r >> 3, c16 = r & 7;
        cp_async16(sA + seg * SEG_B + row * 128 + ((c16 * 16) ^ ((row & 7) * 16)),
                   g_A + (size_t)row * KROW + seg * KSEG + c16 * 8);
    }
    CP_COMMIT();
    CP_WAIT0();
    __syncthreads();

    float sq = 0.0f;

    // per-lane ldsm base rows (fixed per thread)
    const int arowb = wm * 64 + la15;      // + mt*16
    const int browb = wn * 32 + la15;      // + g*16

    for (int mc = 0; mc < M_CHUNKS; mc++) {
        const int m0 = mc * M_TILE;

        float acc[4][4][4];   // [mt][nt8][4]
        #pragma unroll
        for (int i = 0; i < 4; i++)
            #pragma unroll
            for (int j = 0; j < 4; j++)
                #pragma unroll
                for (int k = 0; k < 4; k++) acc[i][j][k] = 0.0f;

        // fragment-reuse mainloop: per ks load Ah,Bh,Bl,Al once; 3 mma passes
        #pragma unroll
        for (int ks = 0; ks < 4; ks++) {
            const uint32_t koff = ks * 32 + half * 16;
            uint32_t ah[4][4], al[4][4], bh[2][4], bl[2][4];
            #pragma unroll
            for (int mt = 0; mt < 4; mt++) {
                int row = arowb + mt * 16;
                ldsm_x4(sA + row * 128 + (koff ^ ((row & 7) * 16)),
                        ah[mt][0], ah[mt][1], ah[mt][2], ah[mt][3]);
            }
            #pragma unroll
            for (int g = 0; g < 2; g++) {
                int row = browb + g * 16;
                ldsm_x4(sB + row * 128 + (koff ^ ((row & 7) * 16)),
                        bh[g][0], bh[g][1], bh[g][2], bh[g][3]);
            }
            // seg0: Ah * Bh
            #pragma unroll
            for (int mt = 0; mt < 4; mt++)
                #pragma unroll
                for (int g = 0; g < 2; g++) {
                    mma16816(acc[mt][2 * g],     ah[mt], bh[g][0], bh[g][2]);
                    mma16816(acc[mt][2 * g + 1], ah[mt], bh[g][1], bh[g][3]);
                }
            // seg1: Ah * Bl
            #pragma unroll
            for (int g = 0; g < 2; g++) {
                int row = browb + g * 16;
                ldsm_x4(sB + SEG_B + row * 128 + (koff ^ ((row & 7) * 16)),
                        bl[g][0], bl[g][1], bl[g][2], bl[g][3]);
            }
            #pragma unroll
            for (int mt = 0; mt < 4; mt++)
                #pragma unroll
                for (int g = 0; g < 2; g++) {
                    mma16816(acc[mt][2 * g],     ah[mt], bl[g][0], bl[g][2]);
                    mma16816(acc[mt][2 * g + 1], ah[mt], bl[g][1], bl[g][3]);
                }
            // seg2: Al * Bh
            #pragma unroll
            for (int mt = 0; mt < 4; mt++) {
                int row = arowb + mt * 16;
                ldsm_x4(sA + SEG_B + row * 128 + (koff ^ ((row & 7) * 16)),
                        al[mt][0], al[mt][1], al[mt][2], al[mt][3]);
            }
            #pragma unroll
            for (int mt = 0; mt < 4; mt++)
                #pragma unroll
                for (int g = 0; g < 2; g++) {
                    mma16816(acc[mt][2 * g],     al[mt], bh[g][0], bh[g][2]);
                    mma16816(acc[mt][2 * g + 1], al[mt], bh[g][1], bh[g][3]);
                }
        }
        __syncthreads();   // all warps done reading A tile

        // --- prefetch next A tile via cp.async (overlaps whole epilogue) ---
        if (mc + 1 < M_CHUNKS) {
            const int m1 = (mc + 1) * M_TILE;
            for (int i = tid; i < 128 * 16; i += 256) {
                int row = i >> 4, r = i & 15, seg = r >> 3, c16 = r & 7;
                cp_async16(sA + seg * SEG_B + row * 128 + ((c16 * 16) ^ ((row & 7) * 16)),
                           g_A + (size_t)(m1 + row) * KROW + seg * KSEG + c16 * 8);
            }
            CP_COMMIT();
        }

        // --- staged epilogue: 2 pairs of 64 cols ---
        #pragma unroll
        for (int pair = 0; pair < 2; pair++) {
            if ((wn >> 1) == pair) {
                const int cbase = (wn & 1) * 32;
                #pragma unroll
                for (int mt = 0; mt < 4; mt++) {
                    int r0 = wm * 64 + mt * 16 + (lane >> 2);
                    #pragma unroll
                    for (int nt = 0; nt < 4; nt++) {
                        int c0 = cbase + nt * 8 + 2 * (lane & 3);
                        float v0 = acc[mt][nt][0], v1 = acc[mt][nt][1];
                        float v2 = acc[mt][nt][2], v3 = acc[mt][nt][3];
                        sq += v0 * v0 + v1 * v1 + v2 * v2 + v3 * v3;
                        stage[r0 * STG_STRIDE + c0]           = v0;
                        stage[r0 * STG_STRIDE + c0 + 1]       = v1;
                        stage[(r0 + 8) * STG_STRIDE + c0]     = v2;
                        stage[(r0 + 8) * STG_STRIDE + c0 + 1] = v3;
                    }
                }
            }
            __syncthreads();
            const int colg = n0 + pair * 64 + lane;
            float* op = out + 1 + (size_t)(m0 + wid * 16) * N_ITEMS;
            #pragma unroll
            for (int r = 0; r < 16; r++) {
                float* rp = op + (size_t)r * N_ITEMS;
                float s0 = stage[(wid * 16 + r) * STG_STRIDE + lane];
                float s1 = stage[(wid * 16 + r) * STG_STRIDE + lane + 32];
                if (colg < N_ITEMS)      rp[colg]      = s0;
                if (colg + 32 < N_ITEMS) rp[colg + 32] = s1;
            }
            if (pair == 0) __syncthreads();   // stores read stage before pair1 overwrites
        }

        CP_WAIT0();
        __syncthreads();   // next A tile fully in smem
    }

    // reduce squares into loss (pad cols contribute exactly 0)
    #pragma unroll
    for (int o = 16; o > 0; o >>= 1) sq += __shfl_xor_sync(0xFFFFFFFFu, sq, o);
    if (lane == 0) atomicAdd(out, sq);
}

// ---------------- positives: + (1 - 2*s) per unique (row, item) ----------------
__global__ void k_pos(const float* __restrict__ user_emb, const float* __restrict__ item_emb,
                      const int* __restrict__ uid, const int* __restrict__ seq,
                      float* __restrict__ out) {
    const int b = blockIdx.x, tid = threadIdx.x;
    const int wid = tid >> 5, lane = tid & 31;
    __shared__ int   s_seq[HIST];
    __shared__ float s_u[IN_CH];
    __shared__ float s_part[4];
    if (tid < HIST)  s_seq[tid] = seq[b * HIST + tid];
    if (tid < IN_CH) s_u[tid]   = user_emb[(size_t)uid[b] * IN_CH + tid];
    if (tid < 4)     s_part[tid] = 0.0f;
    __syncthreads();

    const float u0 = s_u[2 * lane], u1 = s_u[2 * lane + 1];
    float acc = 0.0f;
    for (int j = wid; j < HIST; j += 4) {
        const int idx = s_seq[j];
        bool dup = false;
        for (int jj = 0; jj < j; jj++) dup |= (s_seq[jj] == idx);
        if (!dup) {
            float2 iv = reinterpret_cast<const float2*>(item_emb + (size_t)idx * IN_CH)[lane];
            float p = u0 * iv.x + u1 * iv.y;
            #pragma unroll
            for (int o = 16; o > 0; o >>= 1) p += __shfl_xor_sync(0xFFFFFFFFu, p, o);
            if (lane == 0) acc += 1.0f - 2.0f * p;
        }
    }
    if (lane == 0) s_part[wid] = acc;
    __syncthreads();
    if (tid == 0)
        atomicAdd(out, s_part[0] + s_part[1] + s_part[2] + s_part[3]);
}

// ---------------- launch ----------------
extern "C" void kernel_launch(void* const* d_in, const int* in_sizes, int n_in,
                              void* d_out, int out_size) {
    const float* user_emb = (const float*)d_in[0];
    const float* item_emb = (const float*)d_in[1];
    const int*   uid      = (const int*)d_in[2];
    const int*   seq      = (const int*)d_in[3];
    float*       out      = (float*)d_out;   // [0]=loss, [1..]=pref row-major

    cudaFuncSetAttribute(k_gemm, cudaFuncAttributeMaxDynamicSharedMemorySize, SMEM_TOTAL);

    k_prep<<<(PREP_TOTAL + 255) / 256, 256>>>(user_emb, item_emb, uid, out);
    k_gemm<<<N_CTAS, 256, SMEM_TOTAL>>>(out);
    k_pos<<<BATCH, 128>>>(user_emb, item_emb, uid, seq, out);
}

// round 8
// speedup vs baseline: 1.5686x; 1.0570x over previous
#include <cuda_runtime.h>
#include <cuda_bf16.h>
#include <cstdint>

// ---------------- problem constants ----------------
static constexpr int BATCH    = 1024;
static constexpr int HIST     = 50;
static constexpr int N_ITEMS  = 100000;
static constexpr int IN_CH    = 64;

static constexpr int N_TILE   = 128;              // N per CTA
static constexpr int NPAD     = 100096;           // 782 * 128
static constexpr int N_CTAS   = NPAD / N_TILE;    // 782
static constexpr int M_TILE   = 128;
static constexpr int M_CHUNKS = BATCH / M_TILE;   // 8
static constexpr int KSEG     = 64;               // bf16 per physical seg (=128B row)
static constexpr int KROW     = 2 * KSEG;         // 128 bf16 per A row: [hi | lo]

static constexpr int SEG_B    = 128 * 128;        // bytes per seg tile (128 rows x 128B)
static constexpr int SMEM_A   = 0;                // Ah, Al           (32 KB)
static constexpr int SMEM_B   = 2 * SEG_B;        // Bh, Bl           (32 KB)
static constexpr int SMEM_STG = 4 * SEG_B;        // stage: fp32 B at init, epilogue later
static constexpr int STG_STRIDE = 65;
static constexpr int SMEM_TOTAL = SMEM_STG + 128 * STG_STRIDE * 4;   // 98816 -> 2 CTAs/SM

// scratch: only A needs a global staging buffer (shared across all CTAs)
__device__ __align__(16) __nv_bfloat16 g_A[BATCH * KROW];

// ---------------- helpers ----------------
__device__ __forceinline__ uint32_t smem_u32(const void* p) {
    uint32_t a;
    asm("{ .reg .u64 t; cvta.to.shared.u64 t, %1; cvt.u32.u64 %0, t; }" : "=r"(a) : "l"(p));
    return a;
}
__device__ __forceinline__ void ldsm_x4(uint32_t addr, uint32_t& r0, uint32_t& r1,
                                        uint32_t& r2, uint32_t& r3) {
    asm volatile("ldmatrix.sync.aligned.m8n8.x4.shared.b16 {%0,%1,%2,%3}, [%4];"
                 : "=r"(r0), "=r"(r1), "=r"(r2), "=r"(r3) : "r"(addr));
}
__device__ __forceinline__ void mma16816(float* c, const uint32_t* a, uint32_t b0, uint32_t b1) {
    asm volatile(
        "mma.sync.aligned.m16n8k16.row.col.f32.bf16.bf16.f32 "
        "{%0,%1,%2,%3}, {%4,%5,%6,%7}, {%8,%9}, {%0,%1,%2,%3};"
        : "+f"(c[0]), "+f"(c[1]), "+f"(c[2]), "+f"(c[3])
        : "r"(a[0]), "r"(a[1]), "r"(a[2]), "r"(a[3]), "r"(b0), "r"(b1));
}
__device__ __forceinline__ void cp_async16(uint32_t saddr, const void* gptr) {
    asm volatile("cp.async.cg.shared.global [%0], [%1], 16;" :: "r"(saddr), "l"(gptr));
}
#define CP_COMMIT() asm volatile("cp.async.commit_group;" ::: "memory")
#define CP_WAIT0()  asm volatile("cp.async.wait_group 0;" ::: "memory")

__device__ __forceinline__ void split1(float x, __nv_bfloat16& h, __nv_bfloat16& l) {
    h = __float2bfloat16_rn(x);
    l = __float2bfloat16_rn(x - __bfloat162float(h));
}

// ---------------- tiny prep: init loss + split A (shared by all CTAs) ----------------
__global__ void k_prepA(const float* __restrict__ user_emb, const int* __restrict__ uid,
                        float* __restrict__ out) {
    int gid = blockIdx.x * blockDim.x + threadIdx.x;   // BATCH*16
    if (gid == 0) out[0] = 0.0f;
    int b = gid >> 4, q = gid & 15;
    int u = uid[b];
    float4 v = reinterpret_cast<const float4*>(user_emb)[(size_t)u * 16 + q];
    union { __nv_bfloat16 h[4]; uint2 u2; } H, L;
    split1(v.x, H.h[0], L.h[0]); split1(v.y, H.h[1], L.h[1]);
    split1(v.z, H.h[2], L.h[2]); split1(v.w, H.h[3], L.h[3]);
    __nv_bfloat16* row = g_A + (size_t)b * KROW + q * 4;
    *reinterpret_cast<uint2*>(row)      = H.u2;   // Ah
    *reinterpret_cast<uint2*>(row + 64) = L.u2;   // Al
}

// ---------------- main GEMM + squares ----------------
// CTA: 256 thr = 8 warps, warp grid 2(M) x 4(N), warp tile 64x32. 2 CTAs/SM.
__global__ __launch_bounds__(256, 2) void k_gemm(const float* __restrict__ item_emb,
                                                 float* __restrict__ out) {
    extern __shared__ char smem[];
    const uint32_t sb = smem_u32(smem);
    const uint32_t sA = sb + SMEM_A;
    const uint32_t sB = sb + SMEM_B;
    float* stage = reinterpret_cast<float*>(smem + SMEM_STG);

    const int tid  = threadIdx.x, wid = tid >> 5, lane = tid & 31;
    const int wm   = wid & 1, wn = wid >> 1;
    const int n0   = blockIdx.x * N_TILE;
    const int la15 = lane & 15, half = lane >> 4;

    // --- cp.async: fp32 B rows -> stage, A chunk0 -> sA ---
    for (int i = tid; i < 128 * 16; i += 256) {           // 128 rows x 16 float4
        int row = i >> 4;
        if (n0 + row < N_ITEMS) {
            cp_async16(sb + SMEM_STG + i * 16,
                       item_emb + (size_t)(n0 + row) * IN_CH + (i & 15) * 4);
        } else {
            *reinterpret_cast<float4*>(smem + SMEM_STG + i * 16) = make_float4(0.f, 0.f, 0.f, 0.f);
        }
    }
    for (int i = tid; i < 128 * 16; i += 256) {
        int row = i >> 4, r = i & 15, seg = r >> 3, c16 = r & 7;
        cp_async16(sA + seg * SEG_B + row * 128 + ((c16 * 16) ^ ((row & 7) * 16)),
                   g_A + (size_t)row * KROW + seg * KSEG + c16 * 8);
    }
    CP_COMMIT();
    CP_WAIT0();
    __syncthreads();

    // --- split B in-kernel: stage fp32 -> sB (Bh seg0, Bl seg1), SW128 swizzled ---
    for (int i = tid; i < 128 * 16; i += 256) {
        int row = i >> 4, q = i & 15;
        float4 v = reinterpret_cast<const float4*>(stage)[i];
        union { __nv_bfloat16 h[4]; uint2 u2; } H, L;
        split1(v.x, H.h[0], L.h[0]); split1(v.y, H.h[1], L.h[1]);
        split1(v.z, H.h[2], L.h[2]); split1(v.w, H.h[3], L.h[3]);
        uint32_t off = (uint32_t)(row * 128 + ((q * 8) ^ ((row & 7) * 16)));
        *reinterpret_cast<uint2*>(smem + SMEM_B + off)         = H.u2;   // Bh
        *reinterpret_cast<uint2*>(smem + SMEM_B + SEG_B + off) = L.u2;   // Bl
    }
    __syncthreads();

    float sq = 0.0f;
    const int arowb = wm * 64 + la15;      // + mt*16
    const int browb = wn * 32 + la15;      // + g*16

    for (int mc = 0; mc < M_CHUNKS; mc++) {
        const int m0 = mc * M_TILE;

        float acc[4][4][4];   // [mt][nt8][4]
        #pragma unroll
        for (int i = 0; i < 4; i++)
            #pragma unroll
            for (int j = 0; j < 4; j++)
                #pragma unroll
                for (int k = 0; k < 4; k++) acc[i][j][k] = 0.0f;

        // fragment-reuse mainloop: per ks load Ah,Bh,Bl,Al once; 3 mma passes
        #pragma unroll
        for (int ks = 0; ks < 4; ks++) {
            const uint32_t koff = ks * 32 + half * 16;
            uint32_t ah[4][4], al[4][4], bh[2][4], bl[2][4];
            #pragma unroll
            for (int mt = 0; mt < 4; mt++) {
                int row = arowb + mt * 16;
                ldsm_x4(sA + row * 128 + (koff ^ ((row & 7) * 16)),
                        ah[mt][0], ah[mt][1], ah[mt][2], ah[mt][3]);
            }
            #pragma unroll
            for (int g = 0; g < 2; g++) {
                int row = browb + g * 16;
                ldsm_x4(sB + row * 128 + (koff ^ ((row & 7) * 16)),
                        bh[g][0], bh[g][1], bh[g][2], bh[g][3]);
            }
            // seg0: Ah * Bh
            #pragma unroll
            for (int mt = 0; mt < 4; mt++)
                #pragma unroll
                for (int g = 0; g < 2; g++) {
                    mma16816(acc[mt][2 * g],     ah[mt], bh[g][0], bh[g][2]);
                    mma16816(acc[mt][2 * g + 1], ah[mt], bh[g][1], bh[g][3]);
                }
            // seg1: Ah * Bl
            #pragma unroll
            for (int g = 0; g < 2; g++) {
                int row = browb + g * 16;
                ldsm_x4(sB + SEG_B + row * 128 + (koff ^ ((row & 7) * 16)),
                        bl[g][0], bl[g][1], bl[g][2], bl[g][3]);
            }
            #pragma unroll
            for (int mt = 0; mt < 4; mt++)
                #pragma unroll
                for (int g = 0; g < 2; g++) {
                    mma16816(acc[mt][2 * g],     ah[mt], bl[g][0], bl[g][2]);
                    mma16816(acc[mt][2 * g + 1], ah[mt], bl[g][1], bl[g][3]);
                }
            // seg2: Al * Bh
            #pragma unroll
            for (int mt = 0; mt < 4; mt++) {
                int row = arowb + mt * 16;
                ldsm_x4(sA + SEG_B + row * 128 + (koff ^ ((row & 7) * 16)),
                        al[mt][0], al[mt][1], al[mt][2], al[mt][3]);
            }
            #pragma unroll
            for (int mt = 0; mt < 4; mt++)
                #pragma unroll
                for (int g = 0; g < 2; g++) {
                    mma16816(acc[mt][2 * g],     al[mt], bh[g][0], bh[g][2]);
                    mma16816(acc[mt][2 * g + 1], al[mt], bh[g][1], bh[g][3]);
                }
        }
        __syncthreads();   // all warps done reading A tile

        // --- prefetch next A tile via cp.async (overlaps whole epilogue) ---
        if (mc + 1 < M_CHUNKS) {
            const int m1 = (mc + 1) * M_TILE;
            for (int i = tid; i < 128 * 16; i += 256) {
                int row = i >> 4, r = i & 15, seg = r >> 3, c16 = r & 7;
                cp_async16(sA + seg * SEG_B + row * 128 + ((c16 * 16) ^ ((row & 7) * 16)),
                           g_A + (size_t)(m1 + row) * KROW + seg * KSEG + c16 * 8);
            }
            CP_COMMIT();
        }

        // --- staged epilogue: 2 pairs of 64 cols ---
        #pragma unroll
        for (int pair = 0; pair < 2; pair++) {
            if ((wn >> 1) == pair) {
                const int cbase = (wn & 1) * 32;
                #pragma unroll
                for (int mt = 0; mt < 4; mt++) {
                    int r0 = wm * 64 + mt * 16 + (lane >> 2);
                    #pragma unroll
                    for (int nt = 0; nt < 4; nt++) {
                        int c0 = cbase + nt * 8 + 2 * (lane & 3);
                        float v0 = acc[mt][nt][0], v1 = acc[mt][nt][1];
                        float v2 = acc[mt][nt][2], v3 = acc[mt][nt][3];
                        sq += v0 * v0 + v1 * v1 + v2 * v2 + v3 * v3;
                        stage[r0 * STG_STRIDE + c0]           = v0;
                        stage[r0 * STG_STRIDE + c0 + 1]       = v1;
                        stage[(r0 + 8) * STG_STRIDE + c0]     = v2;
                        stage[(r0 + 8) * STG_STRIDE + c0 + 1] = v3;
                    }
                }
            }
            __syncthreads();
            const int colg = n0 + pair * 64 + lane;
            float* op = out + 1 + (size_t)(m0 + wid * 16) * N_ITEMS;
            #pragma unroll
            for (int r = 0; r < 16; r++) {
                float* rp = op + (size_t)r * N_ITEMS;
                float s0 = stage[(wid * 16 + r) * STG_STRIDE + lane];
                float s1 = stage[(wid * 16 + r) * STG_STRIDE + lane + 32];
                if (colg < N_ITEMS)      rp[colg]      = s0;
                if (colg + 32 < N_ITEMS) rp[colg + 32] = s1;
            }
            if (pair == 0) __syncthreads();   // stores read stage before pair1 overwrites
        }

        CP_WAIT0();
        __syncthreads();   // next A tile fully in smem
    }

    // reduce squares into loss (pad cols contribute exactly 0)
    #pragma unroll
    for (int o = 16; o > 0; o >>= 1) sq += __shfl_xor_sync(0xFFFFFFFFu, sq, o);
    if (lane == 0) atomicAdd(out, sq);
}

// ---------------- positives: + (1 - 2*s) per unique (row, item) ----------------
__global__ void k_pos(const float* __restrict__ user_emb, const float* __restrict__ item_emb,
                      const int* __restrict__ uid, const int* __restrict__ seq,
                      float* __restrict__ out) {
    const int b = blockIdx.x, tid = threadIdx.x;
    const int wid = tid >> 5, lane = tid & 31;
    __shared__ int   s_seq[HIST];
    __shared__ float s_u[IN_CH];
    __shared__ float s_part[4];
    if (tid < HIST)  s_seq[tid] = seq[b * HIST + tid];
    if (tid < IN_CH) s_u[tid]   = user_emb[(size_t)uid[b] * IN_CH + tid];
    if (tid < 4)     s_part[tid] = 0.0f;
    __syncthreads();

    const float u0 = s_u[2 * lane], u1 = s_u[2 * lane + 1];
    float acc = 0.0f;
    for (int j = wid; j < HIST; j += 4) {
        const int idx = s_seq[j];
        bool dup = false;
        for (int jj = 0; jj < j; jj++) dup |= (s_seq[jj] == idx);
        if (!dup) {
            float2 iv = reinterpret_cast<const float2*>(item_emb + (size_t)idx * IN_CH)[lane];
            float p = u0 * iv.x + u1 * iv.y;
            #pragma unroll
            for (int o = 16; o > 0; o >>= 1) p += __shfl_xor_sync(0xFFFFFFFFu, p, o);
            if (lane == 0) acc += 1.0f - 2.0f * p;
        }
    }
    if (lane == 0) s_part[wid] = acc;
    __syncthreads();
    if (tid == 0)
        atomicAdd(out, s_part[0] + s_part[1] + s_part[2] + s_part[3]);
}

// ---------------- launch ----------------
extern "C" void kernel_launch(void* const* d_in, const int* in_sizes, int n_in,
                              void* d_out, int out_size) {
    const float* user_emb = (const float*)d_in[0];
    const float* item_emb = (const float*)d_in[1];
    const int*   uid      = (const int*)d_in[2];
    const int*   seq      = (const int*)d_in[3];
    float*       out      = (float*)d_out;   // [0]=loss, [1..]=pref row-major

    cudaFuncSetAttribute(k_gemm, cudaFuncAttributeMaxDynamicSharedMemorySize, SMEM_TOTAL);

    k_prepA<<<(BATCH * 16) / 256, 256>>>(user_emb, uid, out);
    k_gemm<<<N_CTAS, 256, SMEM_TOTAL>>>(item_emb, out);
    k_pos<<<BATCH, 128>>>(user_emb, item_emb, uid, seq, out);
}

// round 10
// speedup vs baseline: 1.8966x; 1.2091x over previous
#include <cuda_runtime.h>
#include <cuda_fp16.h>
#include <cstdint>

// ---------------- problem constants ----------------
static constexpr int BATCH    = 1024;
static constexpr int HIST     = 50;
static constexpr int N_ITEMS  = 100000;
static constexpr int IN_CH    = 64;

static constexpr int N_TILE   = 128;              // N per CTA
static constexpr int NPAD     = 100096;           // 782 * 128
static constexpr int N_CTAS   = NPAD / N_TILE;    // 782
static constexpr int M_TILE   = 128;
static constexpr int M_CHUNKS = BATCH / M_TILE;   // 8

static constexpr int SEG_B    = 128 * 128;        // bytes per seg tile (128 rows x 128B)
static constexpr int SMEM_A   = 0;                // Ah only          (16 KB)
static constexpr int SMEM_B   = SEG_B;            // Bh, Bl           (32 KB)
static constexpr int SMEM_STG = 3 * SEG_B;        // stage: fp32 B at init (32KB), epilogue later
static constexpr int STG_STRIDE = 65;
static constexpr int SMEM_TOTAL = SMEM_STG + 128 * STG_STRIDE * 4;   // 82432 -> 2 CTAs/SM

// scratch: A hi-half in fp16 (shared across all CTAs)
__device__ __align__(16) __half g_A[BATCH * IN_CH];

// ---------------- helpers ----------------
__device__ __forceinline__ uint32_t smem_u32(const void* p) {
    uint32_t a;
    asm("{ .reg .u64 t; cvta.to.shared.u64 t, %1; cvt.u32.u64 %0, t; }" : "=r"(a) : "l"(p));
    return a;
}
__device__ __forceinline__ void ldsm_x4(uint32_t addr, uint32_t& r0, uint32_t& r1,
                                        uint32_t& r2, uint32_t& r3) {
    asm volatile("ldmatrix.sync.aligned.m8n8.x4.shared.b16 {%0,%1,%2,%3}, [%4];"
                 : "=r"(r0), "=r"(r1), "=r"(r2), "=r"(r3) : "r"(addr));
}
__device__ __forceinline__ void mma16816(float* c, const uint32_t* a, uint32_t b0, uint32_t b1) {
    asm volatile(
        "mma.sync.aligned.m16n8k16.row.col.f32.f16.f16.f32 "
        "{%0,%1,%2,%3}, {%4,%5,%6,%7}, {%8,%9}, {%0,%1,%2,%3};"
        : "+f"(c[0]), "+f"(c[1]), "+f"(c[2]), "+f"(c[3])
        : "r"(a[0]), "r"(a[1]), "r"(a[2]), "r"(a[3]), "r"(b0), "r"(b1));
}
__device__ __forceinline__ void cp_async16(uint32_t saddr, const void* gptr) {
    asm volatile("cp.async.cg.shared.global [%0], [%1], 16;" :: "r"(saddr), "l"(gptr));
}
#define CP_COMMIT() asm volatile("cp.async.commit_group;" ::: "memory")
#define CP_WAIT0()  asm volatile("cp.async.wait_group 0;" ::: "memory")

__device__ __forceinline__ void split_h(float x, __half& h, __half& l) {
    h = __float2half_rn(x);
    l = __float2half_rn(x - __half2float(h));
}

// ---------------- tiny prep: init loss + A -> fp16 hi ----------------
__global__ void k_prepA(const float* __restrict__ user_emb, const int* __restrict__ uid,
                        float* __restrict__ out) {
    int gid = blockIdx.x * blockDim.x + threadIdx.x;   // BATCH*16
    if (gid == 0) out[0] = 0.0f;
    int b = gid >> 4, q = gid & 15;
    int u = uid[b];
    float4 v = reinterpret_cast<const float4*>(user_emb)[(size_t)u * 16 + q];
    union { __half h[4]; uint2 u2; } H;
    H.h[0] = __float2half_rn(v.x); H.h[1] = __float2half_rn(v.y);
    H.h[2] = __float2half_rn(v.z); H.h[3] = __float2half_rn(v.w);
    *reinterpret_cast<uint2*>(g_A + (size_t)b * IN_CH + q * 4) = H.u2;
}

// ---------------- main GEMM + squares ----------------
// CTA: 256 thr = 8 warps, warp grid 2(M) x 4(N), warp tile 64x32. 2 CTAs/SM.
__global__ __launch_bounds__(256, 2) void k_gemm(const float* __restrict__ item_emb,
                                                 float* __restrict__ out) {
    extern __shared__ char smem[];
    const uint32_t sb = smem_u32(smem);
    const uint32_t sA = sb + SMEM_A;
    const uint32_t sB = sb + SMEM_B;
    float* stage = reinterpret_cast<float*>(smem + SMEM_STG);

    const int tid  = threadIdx.x, wid = tid >> 5, lane = tid & 31;
    const int wm   = wid & 1, wn = wid >> 1;
    const int n0   = blockIdx.x * N_TILE;
    const int la15 = lane & 15, half = lane >> 4;

    // --- cp.async: fp32 B rows -> stage, A chunk0 -> sA ---
    for (int i = tid; i < 128 * 16; i += 256) {           // 128 rows x 16 float4
        int row = i >> 4;
        if (n0 + row < N_ITEMS) {
            cp_async16(sb + SMEM_STG + i * 16,
                       item_emb + (size_t)(n0 + row) * IN_CH + (i & 15) * 4);
        } else {
            *reinterpret_cast<float4*>(smem + SMEM_STG + i * 16) = make_float4(0.f, 0.f, 0.f, 0.f);
        }
    }
    for (int i = tid; i < 128 * 8; i += 256) {            // 128 rows x 8 x 16B (fp16)
        int row = i >> 3, c16 = i & 7;
        cp_async16(sA + row * 128 + ((c16 * 16) ^ ((row & 7) * 16)),
                   g_A + (size_t)row * IN_CH + c16 * 8);
    }
    CP_COMMIT();
    CP_WAIT0();
    __syncthreads();

    // --- split B in-kernel: stage fp32 -> sB (Bh seg0, Bl seg1), SW128 swizzled ---
    for (int i = tid; i < 128 * 16; i += 256) {
        int row = i >> 4, q = i & 15;
        float4 v = reinterpret_cast<const float4*>(stage)[i];
        union { __half h[4]; uint2 u2; } H, L;
        split_h(v.x, H.h[0], L.h[0]); split_h(v.y, H.h[1], L.h[1]);
        split_h(v.z, H.h[2], L.h[2]); split_h(v.w, H.h[3], L.h[3]);
        uint32_t off = (uint32_t)(row * 128 + ((q * 8) ^ ((row & 7) * 16)));
        *reinterpret_cast<uint2*>(smem + SMEM_B + off)         = H.u2;   // Bh
        *reinterpret_cast<uint2*>(smem + SMEM_B + SEG_B + off) = L.u2;   // Bl
    }
    __syncthreads();

    float sq = 0.0f;
    const int arowb = wm * 64 + la15;      // + mt*16
    const int browb = wn * 32 + la15;      // + g*16

    for (int mc = 0; mc < M_CHUNKS; mc++) {
        const int m0 = mc * M_TILE;

        float acc[4][4][4];   // [mt][nt8][4]
        #pragma unroll
        for (int i = 0; i < 4; i++)
            #pragma unroll
            for (int j = 0; j < 4; j++)
                #pragma unroll
                for (int k = 0; k < 4; k++) acc[i][j][k] = 0.0f;

        // 2-term mainloop: per ks load Ah, Bh, Bl; mma Ah*Bh then Ah*Bl
        #pragma unroll
        for (int ks = 0; ks < 4; ks++) {
            const uint32_t koff = ks * 32 + half * 16;
            uint32_t ah[4][4], bh[2][4], bl[2][4];
            #pragma unroll
            for (int mt = 0; mt < 4; mt++) {
                int row = arowb + mt * 16;
                ldsm_x4(sA + row * 128 + (koff ^ ((row & 7) * 16)),
                        ah[mt][0], ah[mt][1], ah[mt][2], ah[mt][3]);
            }
            #pragma unroll
            for (int g = 0; g < 2; g++) {
                int row = browb + g * 16;
                ldsm_x4(sB + row * 128 + (koff ^ ((row & 7) * 16)),
                        bh[g][0], bh[g][1], bh[g][2], bh[g][3]);
            }
            #pragma unroll
            for (int g = 0; g < 2; g++) {
                int row = browb + g * 16;
                ldsm_x4(sB + SEG_B + row * 128 + (koff ^ ((row & 7) * 16)),
                        bl[g][0], bl[g][1], bl[g][2], bl[g][3]);
            }
            // term 1: Ah * Bh
            #pragma unroll
            for (int mt = 0; mt < 4; mt++)
                #pragma unroll
                for (int g = 0; g < 2; g++) {
                    mma16816(acc[mt][2 * g],     ah[mt], bh[g][0], bh[g][2]);
                    mma16816(acc[mt][2 * g + 1], ah[mt], bh[g][1], bh[g][3]);
                }
            // term 2: Ah * Bl
            #pragma unroll
            for (int mt = 0; mt < 4; mt++)
                #pragma unroll
                for (int g = 0; g < 2; g++) {
                    mma16816(acc[mt][2 * g],     ah[mt], bl[g][0], bl[g][2]);
                    mma16816(acc[mt][2 * g + 1], ah[mt], bl[g][1], bl[g][3]);
                }
        }
        __syncthreads();   // all warps done reading A tile

        // --- prefetch next A tile via cp.async (overlaps whole epilogue) ---
        if (mc + 1 < M_CHUNKS) {
            const int m1 = (mc + 1) * M_TILE;
            for (int i = tid; i < 128 * 8; i += 256) {
                int row = i >> 3, c16 = i & 7;
                cp_async16(sA + row * 128 + ((c16 * 16) ^ ((row & 7) * 16)),
                           g_A + (size_t)(m1 + row) * IN_CH + c16 * 8);
            }
            CP_COMMIT();
        }

        // --- staged epilogue: 2 pairs of 64 cols ---
        #pragma unroll
        for (int pair = 0; pair < 2; pair++) {
            if ((wn >> 1) == pair) {
                const int cbase = (wn & 1) * 32;
                #pragma unroll
                for (int mt = 0; mt < 4; mt++) {
                    int r0 = wm * 64 + mt * 16 + (lane >> 2);
                    #pragma unroll
                    for (int nt = 0; nt < 4; nt++) {
                        int c0 = cbase + nt * 8 + 2 * (lane & 3);
                        float v0 = acc[mt][nt][0], v1 = acc[mt][nt][1];
                        float v2 = acc[mt][nt][2], v3 = acc[mt][nt][3];
                        sq += v0 * v0 + v1 * v1 + v2 * v2 + v3 * v3;
                        stage[r0 * STG_STRIDE + c0]           = v0;
                        stage[r0 * STG_STRIDE + c0 + 1]       = v1;
                        stage[(r0 + 8) * STG_STRIDE + c0]     = v2;
                        stage[(r0 + 8) * STG_STRIDE + c0 + 1] = v3;
                    }
                }
            }
            __syncthreads();
            const int colg = n0 + pair * 64 + lane;
            float* op = out + 1 + (size_t)(m0 + wid * 16) * N_ITEMS;
            #pragma unroll
            for (int r = 0; r < 16; r++) {
                float* rp = op + (size_t)r * N_ITEMS;
                float s0 = stage[(wid * 16 + r) * STG_STRIDE + lane];
                float s1 = stage[(wid * 16 + r) * STG_STRIDE + lane + 32];
                if (colg < N_ITEMS)      rp[colg]      = s0;
                if (colg + 32 < N_ITEMS) rp[colg + 32] = s1;
            }
            if (pair == 0) __syncthreads();   // stores read stage before pair1 overwrites
        }

        CP_WAIT0();
        __syncthreads();   // next A tile fully in smem
    }

    // reduce squares into loss (pad cols contribute exactly 0)
    #pragma unroll
    for (int o = 16; o > 0; o >>= 1) sq += __shfl_xor_sync(0xFFFFFFFFu, sq, o);
    if (lane == 0) atomicAdd(out, sq);
}

// ---------------- positives: + (1 - 2*s) per unique (row, item) ----------------
// NOTE: s here must match the GEMM's s (loss is sum over the SAME pref values);
// the (1-2s) correction uses the stored pref value; exact fp32 dot differs from
// the fp16 pref by ~2.5e-4 relative, and loss tolerance is enormous (rel 1e-3 of
// ~5e4), so exact fp32 is fine.
__global__ void k_pos(const float* __restrict__ user_emb, const float* __restrict__ item_emb,
                      const int* __restrict__ uid, const int* __restrict__ seq,
                      float* __restrict__ out) {
    const int b = blockIdx.x, tid = threadIdx.x;
    const int wid = tid >> 5, lane = tid & 31;
    __shared__ int   s_seq[HIST];
    __shared__ float s_u[IN_CH];
    __shared__ float s_part[4];
    if (tid < HIST)  s_seq[tid] = seq[b * HIST + tid];
    if (tid < IN_CH) s_u[tid]   = user_emb[(size_t)uid[b] * IN_CH + tid];
    if (tid < 4)     s_part[tid] = 0.0f;
    __syncthreads();

    const float u0 = s_u[2 * lane], u1 = s_u[2 * lane + 1];
    float acc = 0.0f;
    for (int j = wid; j < HIST; j += 4) {
        const int idx = s_seq[j];
        bool dup = false;
        for (int jj = 0; jj < j; jj++) dup |= (s_seq[jj] == idx);
        if (!dup) {
            float2 iv = reinterpret_cast<const float2*>(item_emb + (size_t)idx * IN_CH)[lane];
            float p = u0 * iv.x + u1 * iv.y;
            #pragma unroll
            for (int o = 16; o > 0; o >>= 1) p += __shfl_xor_sync(0xFFFFFFFFu, p, o);
            if (lane == 0) acc += 1.0f - 2.0f * p;
        }
    }
    if (lane == 0) s_part[wid] = acc;
    __syncthreads();
    if (tid == 0)
        atomicAdd(out, s_part[0] + s_part[1] + s_part[2] + s_part[3]);
}

// ---------------- launch ----------------
extern "C" void kernel_launch(void* const* d_in, const int* in_sizes, int n_in,
                              void* d_out, int out_size) {
    const float* user_emb = (const float*)d_in[0];
    const float* item_emb = (const float*)d_in[1];
    const int*   uid      = (const int*)d_in[2];
    const int*   seq      = (const int*)d_in[3];
    float*       out      = (float*)d_out;   // [0]=loss, [1..]=pref row-major

    cudaFuncSetAttribute(k_gemm, cudaFuncAttributeMaxDynamicSharedMemorySize, SMEM_TOTAL);

    k_prepA<<<(BATCH * 16) / 256, 256>>>(user_emb, uid, out);
    k_gemm<<<N_CTAS, 256, SMEM_TOTAL>>>(item_emb, out);
    k_pos<<<BATCH, 128>>>(user_emb, item_emb, uid, seq, out);
}

// round 11
// speedup vs baseline: 2.2117x; 1.1662x over previous
#include <cuda_runtime.h>
#include <cuda_fp16.h>
#include <cstdint>

// ---------------- problem constants ----------------
static constexpr int BATCH    = 1024;
static constexpr int HIST     = 50;
static constexpr int N_ITEMS  = 100000;
static constexpr int IN_CH    = 64;

static constexpr int N_TILE   = 128;              // N per CTA
static constexpr int NPAD     = 100096;           // 782 * 128
static constexpr int N_CTAS   = NPAD / N_TILE;    // 782
static constexpr int M_TILE   = 128;
static constexpr int M_CHUNKS = BATCH / M_TILE;   // 8

static constexpr int SEG_B    = 128 * 128;        // bytes per seg tile (128 rows x 128B)
static constexpr int SMEM_A   = 0;                // Ah only          (16 KB)
static constexpr int SMEM_B   = SEG_B;            // Bh, Bl           (32 KB)
static constexpr int SMEM_STG = 3 * SEG_B;        // stage 128x128 f32, swizzled (64 KB)
static constexpr int SMEM_TOTAL = SMEM_STG + 128 * 128 * 4;   // 114688 -> 2 CTAs/SM

// stage float-index swizzle: conflict-optimal writes (v2) and reads
#define STG_IDX(r, c) ((r) * 128 + ((c) ^ (((r) & 3) << 3)))

// scratch: A hi-half in fp16 (shared across all CTAs)
__device__ __align__(16) __half g_A[BATCH * IN_CH];

// ---------------- helpers ----------------
__device__ __forceinline__ uint32_t smem_u32(const void* p) {
    uint32_t a;
    asm("{ .reg .u64 t; cvta.to.shared.u64 t, %1; cvt.u32.u64 %0, t; }" : "=r"(a) : "l"(p));
    return a;
}
__device__ __forceinline__ void ldsm_x4(uint32_t addr, uint32_t& r0, uint32_t& r1,
                                        uint32_t& r2, uint32_t& r3) {
    asm volatile("ldmatrix.sync.aligned.m8n8.x4.shared.b16 {%0,%1,%2,%3}, [%4];"
                 : "=r"(r0), "=r"(r1), "=r"(r2), "=r"(r3) : "r"(addr));
}
__device__ __forceinline__ void mma16816(float* c, const uint32_t* a, uint32_t b0, uint32_t b1) {
    asm volatile(
        "mma.sync.aligned.m16n8k16.row.col.f32.f16.f16.f32 "
        "{%0,%1,%2,%3}, {%4,%5,%6,%7}, {%8,%9}, {%0,%1,%2,%3};"
        : "+f"(c[0]), "+f"(c[1]), "+f"(c[2]), "+f"(c[3])
        : "r"(a[0]), "r"(a[1]), "r"(a[2]), "r"(a[3]), "r"(b0), "r"(b1));
}
__device__ __forceinline__ void cp_async16(uint32_t saddr, const void* gptr) {
    asm volatile("cp.async.cg.shared.global [%0], [%1], 16;" :: "r"(saddr), "l"(gptr));
}
#define CP_COMMIT() asm volatile("cp.async.commit_group;" ::: "memory")
#define CP_WAIT0()  asm volatile("cp.async.wait_group 0;" ::: "memory")

__device__ __forceinline__ void split_h(float x, __half& h, __half& l) {
    h = __float2half_rn(x);
    l = __float2half_rn(x - __half2float(h));
}

// ---------------- tiny prep: init loss + A -> fp16 hi ----------------
__global__ void k_prepA(const float* __restrict__ user_emb, const int* __restrict__ uid,
                        float* __restrict__ out) {
    int gid = blockIdx.x * blockDim.x + threadIdx.x;   // BATCH*16
    if (gid == 0) out[0] = 0.0f;
    int b = gid >> 4, q = gid & 15;
    int u = uid[b];
    float4 v = reinterpret_cast<const float4*>(user_emb)[(size_t)u * 16 + q];
    union { __half h[4]; uint2 u2; } H;
    H.h[0] = __float2half_rn(v.x); H.h[1] = __float2half_rn(v.y);
    H.h[2] = __float2half_rn(v.z); H.h[3] = __float2half_rn(v.w);
    *reinterpret_cast<uint2*>(g_A + (size_t)b * IN_CH + q * 4) = H.u2;
}

// ---------------- main GEMM + squares ----------------
// CTA: 256 thr = 8 warps, warp grid 2(M) x 4(N), warp tile 64x32. 2 CTAs/SM.
__global__ __launch_bounds__(256, 2) void k_gemm(const float* __restrict__ item_emb,
                                                 float* __restrict__ out) {
    extern __shared__ char smem[];
    const uint32_t sb = smem_u32(smem);
    const uint32_t sA = sb + SMEM_A;
    const uint32_t sB = sb + SMEM_B;
    float* stage = reinterpret_cast<float*>(smem + SMEM_STG);

    const int tid  = threadIdx.x, wid = tid >> 5, lane = tid & 31;
    const int wm   = wid & 1, wn = wid >> 1;
    const int n0   = blockIdx.x * N_TILE;
    const int la15 = lane & 15, half = lane >> 4;

    // --- cp.async: fp32 B rows -> stage, A chunk0 -> sA ---
    for (int i = tid; i < 128 * 16; i += 256) {           // 128 rows x 16 float4
        int row = i >> 4;
        if (n0 + row < N_ITEMS) {
            cp_async16(sb + SMEM_STG + i * 16,
                       item_emb + (size_t)(n0 + row) * IN_CH + (i & 15) * 4);
        } else {
            *reinterpret_cast<float4*>(smem + SMEM_STG + i * 16) = make_float4(0.f, 0.f, 0.f, 0.f);
        }
    }
    for (int i = tid; i < 128 * 8; i += 256) {            // 128 rows x 8 x 16B (fp16)
        int row = i >> 3, c16 = i & 7;
        cp_async16(sA + row * 128 + ((c16 * 16) ^ ((row & 7) * 16)),
                   g_A + (size_t)row * IN_CH + c16 * 8);
    }
    CP_COMMIT();
    CP_WAIT0();
    __syncthreads();

    // --- split B in-kernel: stage fp32 -> sB (Bh seg0, Bl seg1), SW128 swizzled ---
    for (int i = tid; i < 128 * 16; i += 256) {
        int row = i >> 4, q = i & 15;
        float4 v = reinterpret_cast<const float4*>(stage)[i];
        union { __half h[4]; uint2 u2; } H, L;
        split_h(v.x, H.h[0], L.h[0]); split_h(v.y, H.h[1], L.h[1]);
        split_h(v.z, H.h[2], L.h[2]); split_h(v.w, H.h[3], L.h[3]);
        uint32_t off = (uint32_t)(row * 128 + ((q * 8) ^ ((row & 7) * 16)));
        *reinterpret_cast<uint2*>(smem + SMEM_B + off)         = H.u2;   // Bh
        *reinterpret_cast<uint2*>(smem + SMEM_B + SEG_B + off) = L.u2;   // Bl
    }
    __syncthreads();

    float sq = 0.0f;
    const int arowb = wm * 64 + la15;      // + mt*16
    const int browb = wn * 32 + la15;      // + g*16

    for (int mc = 0; mc < M_CHUNKS; mc++) {
        const int m0 = mc * M_TILE;

        float acc[4][4][4];   // [mt][nt8][4]
        #pragma unroll
        for (int i = 0; i < 4; i++)
            #pragma unroll
            for (int j = 0; j < 4; j++)
                #pragma unroll
                for (int k = 0; k < 4; k++) acc[i][j][k] = 0.0f;

        // 2-term mainloop: per ks load Ah, Bh, Bl; mma Ah*Bh then Ah*Bl
        #pragma unroll
        for (int ks = 0; ks < 4; ks++) {
            const uint32_t koff = ks * 32 + half * 16;
            uint32_t ah[4][4], bh[2][4], bl[2][4];
            #pragma unroll
            for (int mt = 0; mt < 4; mt++) {
                int row = arowb + mt * 16;
                ldsm_x4(sA + row * 128 + (koff ^ ((row & 7) * 16)),
                        ah[mt][0], ah[mt][1], ah[mt][2], ah[mt][3]);
            }
            #pragma unroll
            for (int g = 0; g < 2; g++) {
                int row = browb + g * 16;
                ldsm_x4(sB + row * 128 + (koff ^ ((row & 7) * 16)),
                        bh[g][0], bh[g][1], bh[g][2], bh[g][3]);
            }
            #pragma unroll
            for (int g = 0; g < 2; g++) {
                int row = browb + g * 16;
                ldsm_x4(sB + SEG_B + row * 128 + (koff ^ ((row & 7) * 16)),
                        bl[g][0], bl[g][1], bl[g][2], bl[g][3]);
            }
            // term 1: Ah * Bh
            #pragma unroll
            for (int mt = 0; mt < 4; mt++)
                #pragma unroll
                for (int g = 0; g < 2; g++) {
                    mma16816(acc[mt][2 * g],     ah[mt], bh[g][0], bh[g][2]);
                    mma16816(acc[mt][2 * g + 1], ah[mt], bh[g][1], bh[g][3]);
                }
            // term 2: Ah * Bl
            #pragma unroll
            for (int mt = 0; mt < 4; mt++)
                #pragma unroll
                for (int g = 0; g < 2; g++) {
                    mma16816(acc[mt][2 * g],     ah[mt], bl[g][0], bl[g][2]);
                    mma16816(acc[mt][2 * g + 1], ah[mt], bl[g][1], bl[g][3]);
                }
        }
        __syncthreads();   // all warps done reading A tile

        // --- prefetch next A tile via cp.async (overlaps stage + stores) ---
        if (mc + 1 < M_CHUNKS) {
            const int m1 = (mc + 1) * M_TILE;
            for (int i = tid; i < 128 * 8; i += 256) {
                int row = i >> 3, c16 = i & 7;
                cp_async16(sA + row * 128 + ((c16 * 16) ^ ((row & 7) * 16)),
                           g_A + (size_t)(m1 + row) * IN_CH + c16 * 8);
            }
            CP_COMMIT();
        }

        // --- single-pass stage: all 8 warps write their 64x32 region ---
        {
            const int cb = wn * 32;
            #pragma unroll
            for (int mt = 0; mt < 4; mt++) {
                int r0 = wm * 64 + mt * 16 + (lane >> 2);
                #pragma unroll
                for (int nt = 0; nt < 4; nt++) {
                    int c0 = cb + nt * 8 + 2 * (lane & 3);
                    float v0 = acc[mt][nt][0], v1 = acc[mt][nt][1];
                    float v2 = acc[mt][nt][2], v3 = acc[mt][nt][3];
                    sq += v0 * v0 + v1 * v1 + v2 * v2 + v3 * v3;
                    *reinterpret_cast<float2*>(stage + STG_IDX(r0, c0))     = make_float2(v0, v1);
                    *reinterpret_cast<float2*>(stage + STG_IDX(r0 + 8, c0)) = make_float2(v2, v3);
                }
            }
        }
        __syncthreads();

        // --- coalesced stores: warp wid owns rows wid*16..+15, 128 cols ---
        {
            float* op = out + 1 + (size_t)(m0 + wid * 16) * N_ITEMS;
            #pragma unroll
            for (int r = 0; r < 16; r++) {
                const int row = wid * 16 + r;
                float* rp = op + (size_t)r * N_ITEMS;
                #pragma unroll
                for (int k = 0; k < 4; k++) {
                    const int c = k * 32 + lane;
                    if (n0 + c < N_ITEMS)
                        rp[n0 + c] = stage[STG_IDX(row, c)];
                }
            }
        }

        CP_WAIT0();
        __syncthreads();   // stores done reading stage; next A tile in smem
    }

    // reduce squares into loss (pad cols contribute exactly 0)
    #pragma unroll
    for (int o = 16; o > 0; o >>= 1) sq += __shfl_xor_sync(0xFFFFFFFFu, sq, o);
    if (lane == 0) atomicAdd(out, sq);
}

// ---------------- positives: + (1 - 2*s) per unique (row, item) ----------------
__global__ void k_pos(const float* __restrict__ user_emb, const float* __restrict__ item_emb,
                      const int* __restrict__ uid, const int* __restrict__ seq,
                      float* __restrict__ out) {
    const int b = blockIdx.x, tid = threadIdx.x;
    const int wid = tid >> 5, lane = tid & 31;
    __shared__ int   s_seq[HIST];
    __shared__ float s_u[IN_CH];
    __shared__ float s_part[4];
    if (tid < HIST)  s_seq[tid] = seq[b * HIST + tid];
    if (tid < IN_CH) s_u[tid]   = user_emb[(size_t)uid[b] * IN_CH + tid];
    if (tid < 4)     s_part[tid] = 0.0f;
    __syncthreads();

    const float u0 = s_u[2 * lane], u1 = s_u[2 * lane + 1];
    float acc = 0.0f;
    for (int j = wid; j < HIST; j += 4) {
        const int idx = s_seq[j];
        bool dup = false;
        for (int jj = 0; jj < j; jj++) dup |= (s_seq[jj] == idx);
        if (!dup) {
            float2 iv = reinterpret_cast<const float2*>(item_emb + (size_t)idx * IN_CH)[lane];
            float p = u0 * iv.x + u1 * iv.y;
            #pragma unroll
            for (int o = 16; o > 0; o >>= 1) p += __shfl_xor_sync(0xFFFFFFFFu, p, o);
            if (lane == 0) acc += 1.0f - 2.0f * p;
        }
    }
    if (lane == 0) s_part[wid] = acc;
    __syncthreads();
    if (tid == 0)
        atomicAdd(out, s_part[0] + s_part[1] + s_part[2] + s_part[3]);
}

// ---------------- launch ----------------
extern "C" void kernel_launch(void* const* d_in, const int* in_sizes, int n_in,
                              void* d_out, int out_size) {
    const float* user_emb = (const float*)d_in[0];
    const float* item_emb = (const float*)d_in[1];
    const int*   uid      = (const int*)d_in[2];
    const int*   seq      = (const int*)d_in[3];
    float*       out      = (float*)d_out;   // [0]=loss, [1..]=pref row-major

    cudaFuncSetAttribute(k_gemm, cudaFuncAttributeMaxDynamicSharedMemorySize, SMEM_TOTAL);

    k_prepA<<<(BATCH * 16) / 256, 256>>>(user_emb, uid, out);
    k_gemm<<<N_CTAS, 256, SMEM_TOTAL>>>(item_emb, out);
    k_pos<<<BATCH, 128>>>(user_emb, item_emb, uid, seq, out);
}

// round 12
// speedup vs baseline: 2.6050x; 1.1778x over previous
#include <cuda_runtime.h>
#include <cuda_fp16.h>
#include <cstdint>

// ---------------- problem constants ----------------
static constexpr int BATCH    = 1024;
static constexpr int HIST     = 50;
static constexpr int N_ITEMS  = 100000;
static constexpr int IN_CH    = 64;

static constexpr int N_TILE   = 128;              // N per CTA
static constexpr int NPAD     = 100096;           // 782 * 128
static constexpr int N_CTAS   = NPAD / N_TILE;    // 782
static constexpr int M_TILE   = 128;
static constexpr int M_CHUNKS = BATCH / M_TILE;   // 8

static constexpr int SEG_B    = 128 * 128;        // bytes per tile seg (128 rows x 128B)
static constexpr int SMEM_A   = 0;                // Ah               (16 KB)
static constexpr int SMEM_B   = SEG_B;            // Bh               (16 KB)
static constexpr int SMEM_STG = 2 * SEG_B;        // stage 128x128 f32, swizzled (64 KB)
static constexpr int SMEM_TOTAL = SMEM_STG + 128 * 128 * 4;   // 98304 -> 2 CTAs/SM

// stage float-index swizzle: conflict-optimal writes (v2) and reads
#define STG_IDX(r, c) ((r) * 128 + ((c) ^ (((r) & 3) << 3)))

// scratch: A in fp16 (shared across all CTAs)
__device__ __align__(16) __half g_A[BATCH * IN_CH];

// ---------------- helpers ----------------
__device__ __forceinline__ uint32_t smem_u32(const void* p) {
    uint32_t a;
    asm("{ .reg .u64 t; cvta.to.shared.u64 t, %1; cvt.u32.u64 %0, t; }" : "=r"(a) : "l"(p));
    return a;
}
__device__ __forceinline__ void ldsm_x4(uint32_t addr, uint32_t& r0, uint32_t& r1,
                                        uint32_t& r2, uint32_t& r3) {
    asm volatile("ldmatrix.sync.aligned.m8n8.x4.shared.b16 {%0,%1,%2,%3}, [%4];"
                 : "=r"(r0), "=r"(r1), "=r"(r2), "=r"(r3) : "r"(addr));
}
__device__ __forceinline__ void mma16816(float* c, const uint32_t* a, uint32_t b0, uint32_t b1) {
    asm volatile(
        "mma.sync.aligned.m16n8k16.row.col.f32.f16.f16.f32 "
        "{%0,%1,%2,%3}, {%4,%5,%6,%7}, {%8,%9}, {%0,%1,%2,%3};"
        : "+f"(c[0]), "+f"(c[1]), "+f"(c[2]), "+f"(c[3])
        : "r"(a[0]), "r"(a[1]), "r"(a[2]), "r"(a[3]), "r"(b0), "r"(b1));
}
__device__ __forceinline__ void cp_async16(uint32_t saddr, const void* gptr) {
    asm volatile("cp.async.cg.shared.global [%0], [%1], 16;" :: "r"(saddr), "l"(gptr));
}
#define CP_COMMIT() asm volatile("cp.async.commit_group;" ::: "memory")
#define CP_WAIT0()  asm volatile("cp.async.wait_group 0;" ::: "memory")

// ---------------- tiny prep: init loss + A -> fp16 ----------------
__global__ void k_prepA(const float* __restrict__ user_emb, const int* __restrict__ uid,
                        float* __restrict__ out) {
    int gid = blockIdx.x * blockDim.x + threadIdx.x;   // BATCH*16
    if (gid == 0) out[0] = 0.0f;
    int b = gid >> 4, q = gid & 15;
    int u = uid[b];
    float4 v = reinterpret_cast<const float4*>(user_emb)[(size_t)u * 16 + q];
    union { __half h[4]; uint2 u2; } H;
    H.h[0] = __float2half_rn(v.x); H.h[1] = __float2half_rn(v.y);
    H.h[2] = __float2half_rn(v.z); H.h[3] = __float2half_rn(v.w);
    *reinterpret_cast<uint2*>(g_A + (size_t)b * IN_CH + q * 4) = H.u2;
}

// ---------------- main GEMM + squares ----------------
// CTA: 256 thr = 8 warps, warp grid 2(M) x 4(N), warp tile 64x32. 2 CTAs/SM.
__global__ __launch_bounds__(256, 2) void k_gemm(const float* __restrict__ item_emb,
                                                 float* __restrict__ out) {
    extern __shared__ char smem[];
    const uint32_t sb = smem_u32(smem);
    const uint32_t sA = sb + SMEM_A;
    const uint32_t sB = sb + SMEM_B;
    float* stage = reinterpret_cast<float*>(smem + SMEM_STG);

    const int tid  = threadIdx.x, wid = tid >> 5, lane = tid & 31;
    const int wm   = wid & 1, wn = wid >> 1;
    const int n0   = blockIdx.x * N_TILE;
    const int la15 = lane & 15, half = lane >> 4;

    // --- cp.async: fp32 B rows -> stage, A chunk0 -> sA ---
    for (int i = tid; i < 128 * 16; i += 256) {           // 128 rows x 16 float4
        int row = i >> 4;
        if (n0 + row < N_ITEMS) {
            cp_async16(sb + SMEM_STG + i * 16,
                       item_emb + (size_t)(n0 + row) * IN_CH + (i & 15) * 4);
        } else {
            *reinterpret_cast<float4*>(smem + SMEM_STG + i * 16) = make_float4(0.f, 0.f, 0.f, 0.f);
        }
    }
    for (int i = tid; i < 128 * 8; i += 256) {            // 128 rows x 8 x 16B (fp16)
        int row = i >> 3, c16 = i & 7;
        cp_async16(sA + row * 128 + ((c16 * 16) ^ ((row & 7) * 16)),
                   g_A + (size_t)row * IN_CH + c16 * 8);
    }
    CP_COMMIT();
    CP_WAIT0();
    __syncthreads();

    // --- convert B: stage fp32 -> sB fp16, SW128 swizzled ---
    for (int i = tid; i < 128 * 16; i += 256) {
        int row = i >> 4, q = i & 15;
        float4 v = reinterpret_cast<const float4*>(stage)[i];
        union { __half h[4]; uint2 u2; } H;
        H.h[0] = __float2half_rn(v.x); H.h[1] = __float2half_rn(v.y);
        H.h[2] = __float2half_rn(v.z); H.h[3] = __float2half_rn(v.w);
        uint32_t off = (uint32_t)(row * 128 + ((q * 8) ^ ((row & 7) * 16)));
        *reinterpret_cast<uint2*>(smem + SMEM_B + off) = H.u2;
    }
    __syncthreads();

    float sq = 0.0f;
    const int arowb = wm * 64 + la15;      // + mt*16
    const int browb = wn * 32 + la15;      // + g*16

    for (int mc = 0; mc < M_CHUNKS; mc++) {
        const int m0 = mc * M_TILE;

        float acc[4][4][4];   // [mt][nt8][4]
        #pragma unroll
        for (int i = 0; i < 4; i++)
            #pragma unroll
            for (int j = 0; j < 4; j++)
                #pragma unroll
                for (int k = 0; k < 4; k++) acc[i][j][k] = 0.0f;

        // 1-term fp16 mainloop
        #pragma unroll
        for (int ks = 0; ks < 4; ks++) {
            const uint32_t koff = ks * 32 + half * 16;
            uint32_t a[4][4], b[2][4];
            #pragma unroll
            for (int mt = 0; mt < 4; mt++) {
                int row = arowb + mt * 16;
                ldsm_x4(sA + row * 128 + (koff ^ ((row & 7) * 16)),
                        a[mt][0], a[mt][1], a[mt][2], a[mt][3]);
            }
            #pragma unroll
            for (int g = 0; g < 2; g++) {
                int row = browb + g * 16;
                ldsm_x4(sB + row * 128 + (koff ^ ((row & 7) * 16)),
                        b[g][0], b[g][1], b[g][2], b[g][3]);
            }
            #pragma unroll
            for (int mt = 0; mt < 4; mt++)
                #pragma unroll
                for (int g = 0; g < 2; g++) {
                    mma16816(acc[mt][2 * g],     a[mt], b[g][0], b[g][2]);
                    mma16816(acc[mt][2 * g + 1], a[mt], b[g][1], b[g][3]);
                }
        }
        __syncthreads();   // all warps done reading A tile

        // --- prefetch next A tile via cp.async (overlaps stage + stores) ---
        if (mc + 1 < M_CHUNKS) {
            const int m1 = (mc + 1) * M_TILE;
            for (int i = tid; i < 128 * 8; i += 256) {
                int row = i >> 3, c16 = i & 7;
                cp_async16(sA + row * 128 + ((c16 * 16) ^ ((row & 7) * 16)),
                           g_A + (size_t)(m1 + row) * IN_CH + c16 * 8);
            }
            CP_COMMIT();
        }

        // --- single-pass stage: all 8 warps write their 64x32 region ---
        {
            const int cb = wn * 32;
            #pragma unroll
            for (int mt = 0; mt < 4; mt++) {
                int r0 = wm * 64 + mt * 16 + (lane >> 2);
                #pragma unroll
                for (int nt = 0; nt < 4; nt++) {
                    int c0 = cb + nt * 8 + 2 * (lane & 3);
                    float v0 = acc[mt][nt][0], v1 = acc[mt][nt][1];
                    float v2 = acc[mt][nt][2], v3 = acc[mt][nt][3];
                    sq += v0 * v0 + v1 * v1 + v2 * v2 + v3 * v3;
                    *reinterpret_cast<float2*>(stage + STG_IDX(r0, c0))     = make_float2(v0, v1);
                    *reinterpret_cast<float2*>(stage + STG_IDX(r0 + 8, c0)) = make_float2(v2, v3);
                }
            }
        }
        __syncthreads();

        // --- coalesced stores: warp wid owns rows wid*16..+15, 128 cols ---
        {
            float* op = out + 1 + (size_t)(m0 + wid * 16) * N_ITEMS;
            #pragma unroll
            for (int r = 0; r < 16; r++) {
                const int row = wid * 16 + r;
                float* rp = op + (size_t)r * N_ITEMS;
                #pragma unroll
                for (int k = 0; k < 4; k++) {
                    const int c = k * 32 + lane;
                    if (n0 + c < N_ITEMS)
                        rp[n0 + c] = stage[STG_IDX(row, c)];
                }
            }
        }

        CP_WAIT0();
        __syncthreads();   // stores done reading stage; next A tile in smem
    }

    // reduce squares into loss (pad cols contribute exactly 0)
    #pragma unroll
    for (int o = 16; o > 0; o >>= 1) sq += __shfl_xor_sync(0xFFFFFFFFu, sq, o);
    if (lane == 0) atomicAdd(out, sq);
}

// ---------------- positives: + (1 - 2*s) per unique (row, item) ----------------
__global__ void k_pos(const float* __restrict__ user_emb, const float* __restrict__ item_emb,
                      const int* __restrict__ uid, const int* __restrict__ seq,
                      float* __restrict__ out) {
    const int b = blockIdx.x, tid = threadIdx.x;
    const int wid = tid >> 5, lane = tid & 31;
    __shared__ int   s_seq[HIST];
    __shared__ float s_u[IN_CH];
    __shared__ float s_part[4];
    if (tid < HIST)  s_seq[tid] = seq[b * HIST + tid];
    if (tid < IN_CH) s_u[tid]   = user_emb[(size_t)uid[b] * IN_CH + tid];
    if (tid < 4)     s_part[tid] = 0.0f;
    __syncthreads();

    const float u0 = s_u[2 * lane], u1 = s_u[2 * lane + 1];
    float acc = 0.0f;
    for (int j = wid; j < HIST; j += 4) {
        const int idx = s_seq[j];
        bool dup = false;
        for (int jj = 0; jj < j; jj++) dup |= (s_seq[jj] == idx);
        if (!dup) {
            float2 iv = reinterpret_cast<const float2*>(item_emb + (size_t)idx * IN_CH)[lane];
            float p = u0 * iv.x + u1 * iv.y;
            #pragma unroll
            for (int o = 16; o > 0; o >>= 1) p += __shfl_xor_sync(0xFFFFFFFFu, p, o);
            if (lane == 0) acc += 1.0f - 2.0f * p;
        }
    }
    if (lane == 0) s_part[wid] = acc;
    __syncthreads();
    if (tid == 0)
        atomicAdd(out, s_part[0] + s_part[1] + s_part[2] + s_part[3]);
}

// ---------------- launch ----------------
extern "C" void kernel_launch(void* const* d_in, const int* in_sizes, int n_in,
                              void* d_out, int out_size) {
    const float* user_emb = (const float*)d_in[0];
    const float* item_emb = (const float*)d_in[1];
    const int*   uid      = (const int*)d_in[2];
    const int*   seq      = (const int*)d_in[3];
    float*       out      = (float*)d_out;   // [0]=loss, [1..]=pref row-major

    cudaFuncSetAttribute(k_gemm, cudaFuncAttributeMaxDynamicSharedMemorySize, SMEM_TOTAL);

    k_prepA<<<(BATCH * 16) / 256, 256>>>(user_emb, uid, out);
    k_gemm<<<N_CTAS, 256, SMEM_TOTAL>>>(item_emb, out);
    k_pos<<<BATCH, 128>>>(user_emb, item_emb, uid, seq, out);
}